// round 1
// baseline (speedup 1.0000x reference)
#include <cuda_runtime.h>
#include <cstdint>
#include <cstddef>

#define S_N 100000
#define E_N 30000
#define K_N 1000
#define DD 64
#define FF 128
#define B_N 16384
#define NNZ_S 1600000
#define NNZ_E 480000
#define NNZ_K 32000
#define MOM 0.9f
#define LEAK_F 0.1f

static constexpr size_t al256(size_t x) { return (x + 255) & ~(size_t)255; }

// ---------------- static scratch arena ----------------
static constexpr size_t O_ROWPTR_S = 0;
static constexpr size_t O_CURSOR_S = al256(O_ROWPTR_S + (size_t)(S_N + 1) * 4);
static constexpr size_t O_PAIRS_S  = al256(O_CURSOR_S + (size_t)S_N * 4);
static constexpr size_t O_ROWPTR_E = al256(O_PAIRS_S + (size_t)NNZ_S * 8);
static constexpr size_t O_CURSOR_E = al256(O_ROWPTR_E + (size_t)(E_N + 1) * 4);
static constexpr size_t O_PAIRS_E  = al256(O_CURSOR_E + (size_t)E_N * 4);
static constexpr size_t O_ROWPTR_K = al256(O_PAIRS_E + (size_t)NNZ_E * 8);
static constexpr size_t O_CURSOR_K = al256(O_ROWPTR_K + (size_t)(K_N + 1) * 4);
static constexpr size_t O_PAIRS_K  = al256(O_CURSOR_K + (size_t)K_N * 4);
static constexpr size_t O_CUR_S = al256(O_PAIRS_K + (size_t)NNZ_K * 8);
static constexpr size_t O_NXT_S = al256(O_CUR_S + (size_t)S_N * DD * 4);
static constexpr size_t O_ACC_S = al256(O_NXT_S + (size_t)S_N * DD * 4);
static constexpr size_t O_CUR_E = al256(O_ACC_S + (size_t)S_N * DD * 4);
static constexpr size_t O_NXT_E = al256(O_CUR_E + (size_t)E_N * DD * 4);
static constexpr size_t O_ACC_E = al256(O_NXT_E + (size_t)E_N * DD * 4);
static constexpr size_t O_CUR_K = al256(O_ACC_E + (size_t)E_N * DD * 4);
static constexpr size_t O_NXT_K = al256(O_CUR_K + (size_t)K_N * DD * 4);
static constexpr size_t O_ACC_K = al256(O_NXT_K + (size_t)K_N * DD * 4);
static constexpr size_t O_A1    = al256(O_ACC_K + (size_t)K_N * DD * 4);
static constexpr size_t O_A2    = al256(O_A1 + (size_t)B_N * FF * 4);
static constexpr size_t O_BSUMS = al256(O_A2 + (size_t)B_N * FF * 4);
static constexpr size_t ARENA_BYTES = al256(O_BSUMS + 1024 * 4);

__device__ __align__(256) unsigned char g_arena[ARENA_BYTES];

// ---------------- CSR build ----------------
__global__ void zero_int_kernel(int* p, int n) {
    int i = blockIdx.x * blockDim.x + threadIdx.x;
    if (i < n) p[i] = 0;
}

__global__ void hist_kernel(const int* __restrict__ rows, int* __restrict__ rowptr, int nnz) {
    int i = blockIdx.x * blockDim.x + threadIdx.x;
    if (i < nnz) atomicAdd(&rowptr[rows[i] + 1], 1);
}

// inclusive scan of x[0..n), block size 1024, per-block; block totals to bsums
__global__ void scan_block_kernel(int* __restrict__ x, int n, int* __restrict__ bsums) {
    __shared__ int sh[2048];
    int i = blockIdx.x * 1024 + threadIdx.x;
    int v = (i < n) ? x[i] : 0;
    sh[threadIdx.x] = v;
    __syncthreads();
    int cur = 0;
    #pragma unroll
    for (int off = 1; off < 1024; off <<= 1) {
        int val = sh[cur * 1024 + threadIdx.x];
        if ((int)threadIdx.x >= off) val += sh[cur * 1024 + threadIdx.x - off];
        sh[(cur ^ 1) * 1024 + threadIdx.x] = val;
        cur ^= 1;
        __syncthreads();
    }
    if (i < n) x[i] = sh[cur * 1024 + threadIdx.x];
    if (threadIdx.x == 1023) bsums[blockIdx.x] = sh[cur * 1024 + 1023];
}

__global__ void scan_exclusive_single(int* bsums, int nb) {
    if (blockIdx.x == 0 && threadIdx.x == 0) {
        int run = 0;
        for (int i = 0; i < nb; i++) { int v = bsums[i]; bsums[i] = run; run += v; }
    }
}

__global__ void scan_add_kernel(int* __restrict__ x, int n, const int* __restrict__ bsums) {
    int i = blockIdx.x * 1024 + threadIdx.x;
    if (i < n) x[i] += bsums[blockIdx.x];
}

__global__ void copy_int_kernel(int* __restrict__ dst, const int* __restrict__ src, int n) {
    int i = blockIdx.x * blockDim.x + threadIdx.x;
    if (i < n) dst[i] = src[i];
}

__global__ void scatter_kernel(const int* __restrict__ rows, const int* __restrict__ cols,
                               const float* __restrict__ vals, int* __restrict__ cursor,
                               int2* __restrict__ pairs, int nnz) {
    int i = blockIdx.x * blockDim.x + threadIdx.x;
    if (i >= nnz) return;
    int r = rows[i];
    int p = atomicAdd(&cursor[r], 1);
    pairs[p] = make_int2(cols[i], __float_as_int(vals[i]));
}

// ---------------- convolution ----------------
__global__ void init_conv_kernel(const float4* __restrict__ emb, float4* __restrict__ cur,
                                 float4* __restrict__ acc, int n4) {
    int i = blockIdx.x * blockDim.x + threadIdx.x;
    if (i < n4) { float4 v = emb[i]; cur[i] = v; acc[i] = v; }
}

// nxt = spmm(cur) + MOM*cur ; acc += nxt.  64 threads per row (2 warps), d = tid%64.
__global__ void spmm_layer_kernel(const int* __restrict__ rowptr, const int2* __restrict__ pairs,
                                  const float* __restrict__ cur, float* __restrict__ nxt,
                                  float* __restrict__ acc, int nrows) {
    int row = blockIdx.x * 4 + (threadIdx.x >> 6);
    int d = threadIdx.x & 63;
    if (row >= nrows) return;
    int beg = __ldg(rowptr + row);
    int end = __ldg(rowptr + row + 1);
    float s = 0.f;
    for (int j = beg; j < end; j++) {
        int2 p = __ldg(pairs + j);
        s += __int_as_float(p.y) * __ldg(cur + ((size_t)p.x << 6) + d);
    }
    size_t o = ((size_t)row << 6) + d;
    float v = s + MOM * cur[o];
    nxt[o] = v;
    acc[o] += v;
}

// ---------------- dense stage ----------------
// out[r, 0..127] = leaky( (src[id(r)]*scale) @ W + bias ), W is [64][128] row-major
__global__ void __launch_bounds__(256) gemm64_kernel(
    const float* __restrict__ src, const int* __restrict__ ids, float scale,
    const float* __restrict__ W, const float* __restrict__ bias,
    float* __restrict__ out, int rows) {
    __shared__ float Ws[64 * 128];
    __shared__ float Xs[8][64];
    int tid = threadIdx.x;
    const float4* W4 = (const float4*)W;
    float4* Ws4 = (float4*)Ws;
    #pragma unroll
    for (int i = 0; i < 8; i++) Ws4[tid + i * 256] = W4[tid + i * 256];
    int r0 = blockIdx.x * 8;
    if (tid < 128) {
        int rr = tid >> 4;
        int c4 = tid & 15;
        int r = r0 + rr;
        float4 v = make_float4(0.f, 0.f, 0.f, 0.f);
        if (r < rows) {
            int rid = ids ? __ldg(ids + r) : r;
            v = ((const float4*)(src + (size_t)rid * 64))[c4];
        }
        v.x *= scale; v.y *= scale; v.z *= scale; v.w *= scale;
        ((float4*)&Xs[rr][0])[c4] = v;
    }
    __syncthreads();
    int col = tid & 127;
    int rbase = tid >> 7;
    float bv = __ldg(bias + col);
    #pragma unroll
    for (int rr = 0; rr < 4; rr++) {
        int lrow = rr * 2 + rbase;
        int r = r0 + lrow;
        if (r >= rows) continue;
        float a = bv;
        #pragma unroll
        for (int i = 0; i < 64; i++) a = fmaf(Xs[lrow][i], Ws[i * 128 + col], a);
        out[(size_t)r * 128 + col] = (a > 0.f) ? a : LEAK_F * a;
    }
}

__global__ void disc_kernel(const float* __restrict__ acc_e, const int* __restrict__ ids,
                            const float* __restrict__ Wd, const float* __restrict__ bd,
                            float* __restrict__ out, int nrows) {
    int gw = (blockIdx.x * blockDim.x + threadIdx.x) >> 5;
    int lane = threadIdx.x & 31;
    if (gw >= nrows) return;
    int rid = __ldg(ids + gw);
    const float* x = acc_e + (size_t)rid * 64;
    float s = 0.25f * x[lane] * Wd[lane] + 0.25f * x[lane + 32] * Wd[lane + 32];
    #pragma unroll
    for (int o = 16; o; o >>= 1) s += __shfl_xor_sync(0xFFFFFFFFu, s, o);
    if (lane == 0) out[gw] = 1.f / (1.f + __expf(-(s + bd[0])));
}

__global__ void impact_kernel(const float* __restrict__ imp, const int* __restrict__ ids,
                              float* __restrict__ out) {
    int t = blockIdx.x * blockDim.x + threadIdx.x;  // B_N*16 threads
    int b = t >> 4, q = t & 15;
    ((float4*)out)[((size_t)b << 4) + q] =
        ((const float4*)(imp + ((size_t)__ldg(ids + b) << 6)))[q];
}

// O1 = A1 @ Bt^T, O2 = A2 @ Bt^T.  A: [16384,128], Bt: [1000,128], O: [16384,1000]
__global__ void __launch_bounds__(256) big_gemm_dual(
    const float* __restrict__ A1, const float* __restrict__ A2,
    const float* __restrict__ Bt, float* __restrict__ O1, float* __restrict__ O2) {
    __shared__ float As1[32][132];
    __shared__ float As2[32][132];
    __shared__ float Bs[32][68];
    int tid = threadIdx.x;
    int tm = tid >> 4;      // 0..15 -> 8 m-rows each
    int tn = tid & 15;      // 0..15 -> 4 n-cols each
    int m0 = blockIdx.x * 128;
    int n0 = blockIdx.y * 64;
    float acc1[8][4] = {};
    float acc2[8][4] = {};

    for (int kc = 0; kc < 128; kc += 32) {
        #pragma unroll
        for (int i = 0; i < 4; i++) {
            int idx = tid + i * 256;      // 0..1023
            int row = idx >> 3, q = idx & 7;
            float4 v1 = *(const float4*)(A1 + (size_t)(m0 + row) * 128 + kc + q * 4);
            float4 v2 = *(const float4*)(A2 + (size_t)(m0 + row) * 128 + kc + q * 4);
            As1[q * 4 + 0][row] = v1.x; As1[q * 4 + 1][row] = v1.y;
            As1[q * 4 + 2][row] = v1.z; As1[q * 4 + 3][row] = v1.w;
            As2[q * 4 + 0][row] = v2.x; As2[q * 4 + 1][row] = v2.y;
            As2[q * 4 + 2][row] = v2.z; As2[q * 4 + 3][row] = v2.w;
        }
        #pragma unroll
        for (int i = 0; i < 2; i++) {
            int idx = tid + i * 256;      // 0..511
            int row = idx >> 3, q = idx & 7;
            float4 v = make_float4(0.f, 0.f, 0.f, 0.f);
            if (n0 + row < K_N) v = *(const float4*)(Bt + (size_t)(n0 + row) * 128 + kc + q * 4);
            Bs[q * 4 + 0][row] = v.x; Bs[q * 4 + 1][row] = v.y;
            Bs[q * 4 + 2][row] = v.z; Bs[q * 4 + 3][row] = v.w;
        }
        __syncthreads();
        #pragma unroll 4
        for (int kk = 0; kk < 32; kk++) {
            float a1[8], a2[8], bb[4];
            float4 t;
            t = *(const float4*)&As1[kk][tm * 8];     a1[0]=t.x; a1[1]=t.y; a1[2]=t.z; a1[3]=t.w;
            t = *(const float4*)&As1[kk][tm * 8 + 4]; a1[4]=t.x; a1[5]=t.y; a1[6]=t.z; a1[7]=t.w;
            t = *(const float4*)&As2[kk][tm * 8];     a2[0]=t.x; a2[1]=t.y; a2[2]=t.z; a2[3]=t.w;
            t = *(const float4*)&As2[kk][tm * 8 + 4]; a2[4]=t.x; a2[5]=t.y; a2[6]=t.z; a2[7]=t.w;
            t = *(const float4*)&Bs[kk][tn * 4];      bb[0]=t.x; bb[1]=t.y; bb[2]=t.z; bb[3]=t.w;
            #pragma unroll
            for (int i = 0; i < 8; i++)
                #pragma unroll
                for (int j = 0; j < 4; j++) {
                    acc1[i][j] = fmaf(a1[i], bb[j], acc1[i][j]);
                    acc2[i][j] = fmaf(a2[i], bb[j], acc2[i][j]);
                }
        }
        __syncthreads();
    }

    int coln = n0 + tn * 4;
    if (coln < K_N) {
        #pragma unroll
        for (int i = 0; i < 8; i++) {
            size_t row = (size_t)(m0 + tm * 8 + i);
            *(float4*)(O1 + row * K_N + coln) = make_float4(acc1[i][0], acc1[i][1], acc1[i][2], acc1[i][3]);
            *(float4*)(O2 + row * K_N + coln) = make_float4(acc2[i][0], acc2[i][1], acc2[i][2], acc2[i][3]);
        }
    }
}

// ---------------- host orchestration ----------------
static void build_csr(const int* rows, const int* cols, const float* vals,
                      int nnz, int n, int* rowptr, int* cursor, int2* pairs, int* bsums) {
    int ne = n + 1;
    zero_int_kernel<<<(ne + 255) / 256, 256>>>(rowptr, ne);
    hist_kernel<<<(nnz + 255) / 256, 256>>>(rows, rowptr, nnz);
    int nb = (ne + 1023) / 1024;
    scan_block_kernel<<<nb, 1024>>>(rowptr, ne, bsums);
    scan_exclusive_single<<<1, 1>>>(bsums, nb);
    scan_add_kernel<<<nb, 1024>>>(rowptr, ne, bsums);
    copy_int_kernel<<<(n + 255) / 256, 256>>>(cursor, rowptr, n);
    scatter_kernel<<<(nnz + 255) / 256, 256>>>(rows, cols, vals, cursor, pairs, nnz);
}

static void run_conv(const float* emb, const int* rowptr, const int2* pairs,
                     float* cur, float* nxt, float* acc, int n) {
    int n4 = n * DD / 4;
    init_conv_kernel<<<(n4 + 255) / 256, 256>>>((const float4*)emb, (float4*)cur, (float4*)acc, n4);
    float* a = cur; float* b = nxt;
    for (int l = 0; l < 3; l++) {
        spmm_layer_kernel<<<(n + 3) / 4, 256>>>(rowptr, pairs, a, b, acc, n);
        float* t = a; a = b; b = t;
    }
}

extern "C" void kernel_launch(void* const* d_in, const int* in_sizes, int n_in,
                              void* d_out, int out_size) {
    (void)in_sizes; (void)n_in; (void)out_size;
    const int*   student_id  = (const int*)d_in[0];
    const int*   exercise_id = (const int*)d_in[1];
    const float* stu_emb     = (const float*)d_in[3];
    const float* exer_emb    = (const float*)d_in[4];
    const float* know_emb    = (const float*)d_in[5];
    const float* impact_emb  = (const float*)d_in[6];
    const int*   s_rows = (const int*)d_in[7];
    const int*   s_cols = (const int*)d_in[8];
    const float* s_vals = (const float*)d_in[9];
    const int*   e_rows = (const int*)d_in[10];
    const int*   e_cols = (const int*)d_in[11];
    const float* e_vals = (const float*)d_in[12];
    const int*   k_rows = (const int*)d_in[13];
    const int*   k_cols = (const int*)d_in[14];
    const float* k_vals = (const float*)d_in[15];
    const float* W_stu  = (const float*)d_in[16];
    const float* b_stu  = (const float*)d_in[17];
    const float* W_exer = (const float*)d_in[18];
    const float* b_exer = (const float*)d_in[19];
    const float* W_know = (const float*)d_in[20];
    const float* b_know = (const float*)d_in[21];
    const float* W_disc = (const float*)d_in[22];
    const float* b_disc = (const float*)d_in[23];

    unsigned char* A = nullptr;
    cudaGetSymbolAddress((void**)&A, g_arena);

    int*   rowptr_s = (int*)(A + O_ROWPTR_S);
    int*   cursor_s = (int*)(A + O_CURSOR_S);
    int2*  pairs_s  = (int2*)(A + O_PAIRS_S);
    int*   rowptr_e = (int*)(A + O_ROWPTR_E);
    int*   cursor_e = (int*)(A + O_CURSOR_E);
    int2*  pairs_e  = (int2*)(A + O_PAIRS_E);
    int*   rowptr_k = (int*)(A + O_ROWPTR_K);
    int*   cursor_k = (int*)(A + O_CURSOR_K);
    int2*  pairs_k  = (int2*)(A + O_PAIRS_K);
    float* cur_s = (float*)(A + O_CUR_S);
    float* nxt_s = (float*)(A + O_NXT_S);
    float* acc_s = (float*)(A + O_ACC_S);
    float* cur_e = (float*)(A + O_CUR_E);
    float* nxt_e = (float*)(A + O_NXT_E);
    float* acc_e = (float*)(A + O_ACC_E);
    float* cur_k = (float*)(A + O_CUR_K);
    float* nxt_k = (float*)(A + O_NXT_K);
    float* acc_k = (float*)(A + O_ACC_K);
    float* A1    = (float*)(A + O_A1);
    float* A2    = (float*)(A + O_A2);
    int*   bsums = (int*)(A + O_BSUMS);

    // 1) CSR builds
    build_csr(s_rows, s_cols, s_vals, NNZ_S, S_N, rowptr_s, cursor_s, pairs_s, bsums);
    build_csr(e_rows, e_cols, e_vals, NNZ_E, E_N, rowptr_e, cursor_e, pairs_e, bsums);
    build_csr(k_rows, k_cols, k_vals, NNZ_K, K_N, rowptr_k, cursor_k, pairs_k, bsums);

    // 2) convolutions
    run_conv(stu_emb,  rowptr_s, pairs_s, cur_s, nxt_s, acc_s, S_N);
    run_conv(exer_emb, rowptr_e, pairs_e, cur_e, nxt_e, acc_e, E_N);
    run_conv(know_emb, rowptr_k, pairs_k, cur_k, nxt_k, acc_k, K_N);

    // 3) output layout
    float* out   = (float*)d_out;
    float* O1    = out;                                 // student_ts [B,K]
    float* O2    = O1 + (size_t)B_N * K_N;              // diff_ts [B,K]
    float* Odisc = O2 + (size_t)B_N * K_N;              // disc [B,1]
    float* Okt   = Odisc + B_N;                         // knowledge_ts [K,F]
    float* Oimp  = Okt + (size_t)K_N * FF;              // impact [B,D]

    // 4) small dense stage (gather + /4 fused as scale)
    gemm64_kernel<<<B_N / 8, 256>>>(acc_s, student_id, 0.25f, W_stu, b_stu, A1, B_N);
    gemm64_kernel<<<B_N / 8, 256>>>(acc_e, exercise_id, 0.25f, W_exer, b_exer, A2, B_N);
    gemm64_kernel<<<K_N / 8, 256>>>(acc_k, nullptr, 0.25f, W_know, b_know, Okt, K_N);
    disc_kernel<<<B_N / 8, 256>>>(acc_e, exercise_id, W_disc, b_disc, Odisc, B_N);
    impact_kernel<<<B_N * 16 / 256, 256>>>(impact_emb, exercise_id, Oimp);

    // 5) fused big GEMM pair: O1 = A1 @ Okt^T, O2 = A2 @ Okt^T
    dim3 grid(B_N / 128, (K_N + 63) / 64);
    big_gemm_dual<<<grid, 256>>>(A1, A2, Okt, O1, O2);
}

// round 2
// speedup vs baseline: 1.2369x; 1.2369x over previous
#include <cuda_runtime.h>
#include <cstdint>
#include <cstddef>

#define S_N 100000
#define E_N 30000
#define K_N 1000
#define DD 64
#define FF 128
#define B_N 16384
#define NNZ_S 1600000
#define NNZ_E 480000
#define NNZ_K 32000
#define MOM 0.9f
#define LEAK_F 0.1f

static constexpr size_t al256(size_t x) { return (x + 255) & ~(size_t)255; }

// ---------------- static scratch arena ----------------
static constexpr size_t O_ROWPTR_S = 0;
static constexpr size_t O_CURSOR_S = al256(O_ROWPTR_S + (size_t)(S_N + 1) * 4);
static constexpr size_t O_PAIRS_S  = al256(O_CURSOR_S + (size_t)S_N * 4);
static constexpr size_t O_ROWPTR_E = al256(O_PAIRS_S + (size_t)NNZ_S * 8);
static constexpr size_t O_CURSOR_E = al256(O_ROWPTR_E + (size_t)(E_N + 1) * 4);
static constexpr size_t O_PAIRS_E  = al256(O_CURSOR_E + (size_t)E_N * 4);
static constexpr size_t O_ROWPTR_K = al256(O_PAIRS_E + (size_t)NNZ_E * 8);
static constexpr size_t O_CURSOR_K = al256(O_ROWPTR_K + (size_t)(K_N + 1) * 4);
static constexpr size_t O_PAIRS_K  = al256(O_CURSOR_K + (size_t)K_N * 4);
static constexpr size_t O_CUR_S = al256(O_PAIRS_K + (size_t)NNZ_K * 8);
static constexpr size_t O_NXT_S = al256(O_CUR_S + (size_t)S_N * DD * 4);
static constexpr size_t O_ACC_S = al256(O_NXT_S + (size_t)S_N * DD * 4);
static constexpr size_t O_CUR_E = al256(O_ACC_S + (size_t)S_N * DD * 4);
static constexpr size_t O_NXT_E = al256(O_CUR_E + (size_t)E_N * DD * 4);
static constexpr size_t O_ACC_E = al256(O_NXT_E + (size_t)E_N * DD * 4);
static constexpr size_t O_CUR_K = al256(O_ACC_E + (size_t)E_N * DD * 4);
static constexpr size_t O_NXT_K = al256(O_CUR_K + (size_t)K_N * DD * 4);
static constexpr size_t O_ACC_K = al256(O_NXT_K + (size_t)K_N * DD * 4);
static constexpr size_t O_A1    = al256(O_ACC_K + (size_t)K_N * DD * 4);
static constexpr size_t O_A2    = al256(O_A1 + (size_t)B_N * FF * 4);
static constexpr size_t O_BSUMS = al256(O_A2 + (size_t)B_N * FF * 4);
static constexpr size_t ARENA_BYTES = al256(O_BSUMS + 1024 * 4);

__device__ __align__(256) unsigned char g_arena[ARENA_BYTES];

// ---------------- CSR build ----------------
__global__ void zero_int_kernel(int* p, int n) {
    int i = blockIdx.x * blockDim.x + threadIdx.x;
    if (i < n) p[i] = 0;
}

__global__ void hist_kernel(const int* __restrict__ rows, int* __restrict__ rowptr, int nnz) {
    int i = blockIdx.x * blockDim.x + threadIdx.x;
    if (i < nnz) atomicAdd(&rowptr[rows[i] + 1], 1);
}

// inclusive scan of x[0..n), block size 1024, per-block; block totals to bsums
__global__ void scan_block_kernel(int* __restrict__ x, int n, int* __restrict__ bsums) {
    __shared__ int sh[2048];
    int i = blockIdx.x * 1024 + threadIdx.x;
    int v = (i < n) ? x[i] : 0;
    sh[threadIdx.x] = v;
    __syncthreads();
    int cur = 0;
    #pragma unroll
    for (int off = 1; off < 1024; off <<= 1) {
        int val = sh[cur * 1024 + threadIdx.x];
        if ((int)threadIdx.x >= off) val += sh[cur * 1024 + threadIdx.x - off];
        sh[(cur ^ 1) * 1024 + threadIdx.x] = val;
        cur ^= 1;
        __syncthreads();
    }
    if (i < n) x[i] = sh[cur * 1024 + threadIdx.x];
    if (threadIdx.x == 1023) bsums[blockIdx.x] = sh[cur * 1024 + 1023];
}

// parallel exclusive scan of bsums[0..nb), nb <= 128, single block of 128
__global__ void scan_bsums_kernel(int* __restrict__ bsums, int nb) {
    __shared__ int sh[256];
    int t = threadIdx.x;
    int v = (t < nb) ? bsums[t] : 0;
    sh[t] = v;
    __syncthreads();
    int cur = 0;
    #pragma unroll
    for (int off = 1; off < 128; off <<= 1) {
        int val = sh[cur * 128 + t];
        if (t >= off) val += sh[cur * 128 + t - off];
        sh[(cur ^ 1) * 128 + t] = val;
        cur ^= 1;
        __syncthreads();
    }
    if (t < nb) bsums[t] = sh[cur * 128 + t] - v;   // exclusive
}

__global__ void scan_add_kernel(int* __restrict__ x, int n, const int* __restrict__ bsums) {
    int i = blockIdx.x * 1024 + threadIdx.x;
    if (i < n) x[i] += bsums[blockIdx.x];
}

__global__ void copy_int_kernel(int* __restrict__ dst, const int* __restrict__ src, int n) {
    int i = blockIdx.x * blockDim.x + threadIdx.x;
    if (i < n) dst[i] = src[i];
}

__global__ void scatter_kernel(const int* __restrict__ rows, const int* __restrict__ cols,
                               const float* __restrict__ vals, int* __restrict__ cursor,
                               int2* __restrict__ pairs, int nnz) {
    int i = blockIdx.x * blockDim.x + threadIdx.x;
    if (i >= nnz) return;
    int r = rows[i];
    int p = atomicAdd(&cursor[r], 1);
    pairs[p] = make_int2(cols[i], __float_as_int(vals[i]));
}

// ---------------- convolution ----------------
__global__ void init_conv_kernel(const float4* __restrict__ emb, float4* __restrict__ cur,
                                 float4* __restrict__ acc, int n4) {
    int i = blockIdx.x * blockDim.x + threadIdx.x;
    if (i < n4) { float4 v = emb[i]; cur[i] = v; acc[i] = v; }
}

// nxt = spmm(cur) + MOM*cur ; acc += nxt.  64 threads per row (2 warps), d = tid%64.
__global__ void spmm_layer_kernel(const int* __restrict__ rowptr, const int2* __restrict__ pairs,
                                  const float* __restrict__ cur, float* __restrict__ nxt,
                                  float* __restrict__ acc, int nrows) {
    int row = blockIdx.x * 4 + (threadIdx.x >> 6);
    int d = threadIdx.x & 63;
    if (row >= nrows) return;
    int beg = __ldg(rowptr + row);
    int end = __ldg(rowptr + row + 1);
    float s = 0.f;
    for (int j = beg; j < end; j++) {
        int2 p = __ldg(pairs + j);
        s += __int_as_float(p.y) * __ldg(cur + ((size_t)p.x << 6) + d);
    }
    size_t o = ((size_t)row << 6) + d;
    float v = s + MOM * cur[o];
    nxt[o] = v;
    acc[o] += v;
}

// ---------------- dense stage ----------------
__global__ void __launch_bounds__(256) gemm64_kernel(
    const float* __restrict__ src, const int* __restrict__ ids, float scale,
    const float* __restrict__ W, const float* __restrict__ bias,
    float* __restrict__ out, int rows) {
    __shared__ float Ws[64 * 128];
    __shared__ float Xs[8][64];
    int tid = threadIdx.x;
    const float4* W4 = (const float4*)W;
    float4* Ws4 = (float4*)Ws;
    #pragma unroll
    for (int i = 0; i < 8; i++) Ws4[tid + i * 256] = W4[tid + i * 256];
    int r0 = blockIdx.x * 8;
    if (tid < 128) {
        int rr = tid >> 4;
        int c4 = tid & 15;
        int r = r0 + rr;
        float4 v = make_float4(0.f, 0.f, 0.f, 0.f);
        if (r < rows) {
            int rid = ids ? __ldg(ids + r) : r;
            v = ((const float4*)(src + (size_t)rid * 64))[c4];
        }
        v.x *= scale; v.y *= scale; v.z *= scale; v.w *= scale;
        ((float4*)&Xs[rr][0])[c4] = v;
    }
    __syncthreads();
    int col = tid & 127;
    int rbase = tid >> 7;
    float bv = __ldg(bias + col);
    #pragma unroll
    for (int rr = 0; rr < 4; rr++) {
        int lrow = rr * 2 + rbase;
        int r = r0 + lrow;
        if (r >= rows) continue;
        float a = bv;
        #pragma unroll
        for (int i = 0; i < 64; i++) a = fmaf(Xs[lrow][i], Ws[i * 128 + col], a);
        out[(size_t)r * 128 + col] = (a > 0.f) ? a : LEAK_F * a;
    }
}

__global__ void disc_kernel(const float* __restrict__ acc_e, const int* __restrict__ ids,
                            const float* __restrict__ Wd, const float* __restrict__ bd,
                            float* __restrict__ out, int nrows) {
    int gw = (blockIdx.x * blockDim.x + threadIdx.x) >> 5;
    int lane = threadIdx.x & 31;
    if (gw >= nrows) return;
    int rid = __ldg(ids + gw);
    const float* x = acc_e + (size_t)rid * 64;
    float s = 0.25f * x[lane] * Wd[lane] + 0.25f * x[lane + 32] * Wd[lane + 32];
    #pragma unroll
    for (int o = 16; o; o >>= 1) s += __shfl_xor_sync(0xFFFFFFFFu, s, o);
    if (lane == 0) out[gw] = 1.f / (1.f + __expf(-(s + bd[0])));
}

__global__ void impact_kernel(const float* __restrict__ imp, const int* __restrict__ ids,
                              float* __restrict__ out) {
    int t = blockIdx.x * blockDim.x + threadIdx.x;  // B_N*16 threads
    int b = t >> 4, q = t & 15;
    ((float4*)out)[((size_t)b << 4) + q] =
        ((const float4*)(imp + ((size_t)__ldg(ids + b) << 6)))[q];
}

// ---------------- TF32 tensor-core big GEMM ----------------
// O1 = A1 @ Bt^T, O2 = A2 @ Bt^T.  A: [16384,128], Bt: [1000,128], O: [16384,1000]
// mma.sync.m16n8k8 tf32. Block = 256 thr = 8 warps, tile 128(M) x 64(N), dual-A.
__device__ __forceinline__ uint32_t f2tf32(float f) {
    uint32_t u;
    asm("cvt.rna.tf32.f32 %0, %1;" : "=r"(u) : "f"(f));
    return u;
}

#define MMA_TF32(d, a, b)                                                     \
    asm volatile(                                                             \
        "mma.sync.aligned.m16n8k8.row.col.f32.tf32.tf32.f32 "                 \
        "{%0,%1,%2,%3}, {%4,%5,%6,%7}, {%8,%9}, {%0,%1,%2,%3};\n"             \
        : "+f"(d[0]), "+f"(d[1]), "+f"(d[2]), "+f"(d[3])                      \
        : "r"(a[0]), "r"(a[1]), "r"(a[2]), "r"(a[3]), "r"(b[0]), "r"(b[1]))

#define SMPAD 36

__global__ void __launch_bounds__(256) big_gemm_tf32_dual(
    const float* __restrict__ A1, const float* __restrict__ A2,
    const float* __restrict__ Bt, float* __restrict__ O1, float* __restrict__ O2) {
    __shared__ uint32_t As1[128 * SMPAD];
    __shared__ uint32_t As2[128 * SMPAD];
    __shared__ uint32_t Bs[64 * SMPAD];

    int tid = threadIdx.x;
    int warp = tid >> 5;
    int lane = tid & 31;
    int g = lane >> 2;        // groupID
    int tg = lane & 3;        // thread-in-group
    int wm = warp & 3;        // m quadrant (32 rows)
    int wn = warp >> 2;       // n half (32 cols)
    int m0 = blockIdx.x * 128;
    int n0 = blockIdx.y * 64;

    float acc1[2][4][4] = {};
    float acc2[2][4][4] = {};

    for (int kc = 0; kc < 128; kc += 32) {
        // load A1/A2 chunk [128 rows x 32 k] as tf32
        #pragma unroll
        for (int i = 0; i < 4; i++) {
            int idx = tid + i * 256;          // 0..1023 float4 slots
            int row = idx >> 3, q = idx & 7;
            const float4 v1 = *(const float4*)(A1 + (size_t)(m0 + row) * 128 + kc + q * 4);
            const float4 v2 = *(const float4*)(A2 + (size_t)(m0 + row) * 128 + kc + q * 4);
            uint32_t* p1 = &As1[row * SMPAD + q * 4];
            uint32_t* p2 = &As2[row * SMPAD + q * 4];
            p1[0] = f2tf32(v1.x); p1[1] = f2tf32(v1.y); p1[2] = f2tf32(v1.z); p1[3] = f2tf32(v1.w);
            p2[0] = f2tf32(v2.x); p2[1] = f2tf32(v2.y); p2[2] = f2tf32(v2.z); p2[3] = f2tf32(v2.w);
        }
        // load B chunk [64 n-rows x 32 k]
        #pragma unroll
        for (int i = 0; i < 2; i++) {
            int idx = tid + i * 256;          // 0..511
            int row = idx >> 3, q = idx & 7;
            float4 v = make_float4(0.f, 0.f, 0.f, 0.f);
            if (n0 + row < K_N) v = *(const float4*)(Bt + (size_t)(n0 + row) * 128 + kc + q * 4);
            uint32_t* p = &Bs[row * SMPAD + q * 4];
            p[0] = f2tf32(v.x); p[1] = f2tf32(v.y); p[2] = f2tf32(v.z); p[3] = f2tf32(v.w);
        }
        __syncthreads();

        #pragma unroll
        for (int ks = 0; ks < 4; ks++) {
            int k0 = ks * 8;
            uint32_t b[4][2];
            #pragma unroll
            for (int nt = 0; nt < 4; nt++) {
                const uint32_t* bp = &Bs[(wn * 32 + nt * 8 + g) * SMPAD + k0 + tg];
                b[nt][0] = bp[0];
                b[nt][1] = bp[4];
            }
            #pragma unroll
            for (int mt = 0; mt < 2; mt++) {
                uint32_t a[4];
                const uint32_t* ap0 = &As1[(wm * 32 + mt * 16 + g) * SMPAD + k0 + tg];
                a[0] = ap0[0];
                a[1] = ap0[8 * SMPAD];
                a[2] = ap0[4];
                a[3] = ap0[8 * SMPAD + 4];
                #pragma unroll
                for (int nt = 0; nt < 4; nt++) MMA_TF32(acc1[mt][nt], a, b[nt]);
                const uint32_t* ap1 = &As2[(wm * 32 + mt * 16 + g) * SMPAD + k0 + tg];
                a[0] = ap1[0];
                a[1] = ap1[8 * SMPAD];
                a[2] = ap1[4];
                a[3] = ap1[8 * SMPAD + 4];
                #pragma unroll
                for (int nt = 0; nt < 4; nt++) MMA_TF32(acc2[mt][nt], a, b[nt]);
            }
        }
        __syncthreads();
    }

    // epilogue
    #pragma unroll
    for (int mt = 0; mt < 2; mt++) {
        #pragma unroll
        for (int nt = 0; nt < 4; nt++) {
            int col = n0 + wn * 32 + nt * 8 + tg * 2;
            if (col >= K_N) continue;
            size_t r0 = (size_t)(m0 + wm * 32 + mt * 16 + g);
            size_t r1 = r0 + 8;
            *(float2*)(O1 + r0 * K_N + col) = make_float2(acc1[mt][nt][0], acc1[mt][nt][1]);
            *(float2*)(O1 + r1 * K_N + col) = make_float2(acc1[mt][nt][2], acc1[mt][nt][3]);
            *(float2*)(O2 + r0 * K_N + col) = make_float2(acc2[mt][nt][0], acc2[mt][nt][1]);
            *(float2*)(O2 + r1 * K_N + col) = make_float2(acc2[mt][nt][2], acc2[mt][nt][3]);
        }
    }
}

// ---------------- host orchestration ----------------
static void build_csr(const int* rows, const int* cols, const float* vals,
                      int nnz, int n, int* rowptr, int* cursor, int2* pairs, int* bsums) {
    int ne = n + 1;
    zero_int_kernel<<<(ne + 255) / 256, 256>>>(rowptr, ne);
    hist_kernel<<<(nnz + 255) / 256, 256>>>(rows, rowptr, nnz);
    int nb = (ne + 1023) / 1024;
    scan_block_kernel<<<nb, 1024>>>(rowptr, ne, bsums);
    scan_bsums_kernel<<<1, 128>>>(bsums, nb);
    scan_add_kernel<<<nb, 1024>>>(rowptr, ne, bsums);
    copy_int_kernel<<<(n + 255) / 256, 256>>>(cursor, rowptr, n);
    scatter_kernel<<<(nnz + 255) / 256, 256>>>(rows, cols, vals, cursor, pairs, nnz);
}

static void run_conv(const float* emb, const int* rowptr, const int2* pairs,
                     float* cur, float* nxt, float* acc, int n) {
    int n4 = n * DD / 4;
    init_conv_kernel<<<(n4 + 255) / 256, 256>>>((const float4*)emb, (float4*)cur, (float4*)acc, n4);
    float* a = cur; float* b = nxt;
    for (int l = 0; l < 3; l++) {
        spmm_layer_kernel<<<(n + 3) / 4, 256>>>(rowptr, pairs, a, b, acc, n);
        float* t = a; a = b; b = t;
    }
}

extern "C" void kernel_launch(void* const* d_in, const int* in_sizes, int n_in,
                              void* d_out, int out_size) {
    (void)in_sizes; (void)n_in; (void)out_size;
    const int*   student_id  = (const int*)d_in[0];
    const int*   exercise_id = (const int*)d_in[1];
    const float* stu_emb     = (const float*)d_in[3];
    const float* exer_emb    = (const float*)d_in[4];
    const float* know_emb    = (const float*)d_in[5];
    const float* impact_emb  = (const float*)d_in[6];
    const int*   s_rows = (const int*)d_in[7];
    const int*   s_cols = (const int*)d_in[8];
    const float* s_vals = (const float*)d_in[9];
    const int*   e_rows = (const int*)d_in[10];
    const int*   e_cols = (const int*)d_in[11];
    const float* e_vals = (const float*)d_in[12];
    const int*   k_rows = (const int*)d_in[13];
    const int*   k_cols = (const int*)d_in[14];
    const float* k_vals = (const float*)d_in[15];
    const float* W_stu  = (const float*)d_in[16];
    const float* b_stu  = (const float*)d_in[17];
    const float* W_exer = (const float*)d_in[18];
    const float* b_exer = (const float*)d_in[19];
    const float* W_know = (const float*)d_in[20];
    const float* b_know = (const float*)d_in[21];
    const float* W_disc = (const float*)d_in[22];
    const float* b_disc = (const float*)d_in[23];

    unsigned char* A = nullptr;
    cudaGetSymbolAddress((void**)&A, g_arena);

    int*   rowptr_s = (int*)(A + O_ROWPTR_S);
    int*   cursor_s = (int*)(A + O_CURSOR_S);
    int2*  pairs_s  = (int2*)(A + O_PAIRS_S);
    int*   rowptr_e = (int*)(A + O_ROWPTR_E);
    int*   cursor_e = (int*)(A + O_CURSOR_E);
    int2*  pairs_e  = (int2*)(A + O_PAIRS_E);
    int*   rowptr_k = (int*)(A + O_ROWPTR_K);
    int*   cursor_k = (int*)(A + O_CURSOR_K);
    int2*  pairs_k  = (int2*)(A + O_PAIRS_K);
    float* cur_s = (float*)(A + O_CUR_S);
    float* nxt_s = (float*)(A + O_NXT_S);
    float* acc_s = (float*)(A + O_ACC_S);
    float* cur_e = (float*)(A + O_CUR_E);
    float* nxt_e = (float*)(A + O_NXT_E);
    float* acc_e = (float*)(A + O_ACC_E);
    float* cur_k = (float*)(A + O_CUR_K);
    float* nxt_k = (float*)(A + O_NXT_K);
    float* acc_k = (float*)(A + O_ACC_K);
    float* A1    = (float*)(A + O_A1);
    float* A2    = (float*)(A + O_A2);
    int*   bsums = (int*)(A + O_BSUMS);

    // 1) CSR builds
    build_csr(s_rows, s_cols, s_vals, NNZ_S, S_N, rowptr_s, cursor_s, pairs_s, bsums);
    build_csr(e_rows, e_cols, e_vals, NNZ_E, E_N, rowptr_e, cursor_e, pairs_e, bsums);
    build_csr(k_rows, k_cols, k_vals, NNZ_K, K_N, rowptr_k, cursor_k, pairs_k, bsums);

    // 2) convolutions
    run_conv(stu_emb,  rowptr_s, pairs_s, cur_s, nxt_s, acc_s, S_N);
    run_conv(exer_emb, rowptr_e, pairs_e, cur_e, nxt_e, acc_e, E_N);
    run_conv(know_emb, rowptr_k, pairs_k, cur_k, nxt_k, acc_k, K_N);

    // 3) output layout
    float* out   = (float*)d_out;
    float* O1    = out;                                 // student_ts [B,K]
    float* O2    = O1 + (size_t)B_N * K_N;              // diff_ts [B,K]
    float* Odisc = O2 + (size_t)B_N * K_N;              // disc [B,1]
    float* Okt   = Odisc + B_N;                         // knowledge_ts [K,F]
    float* Oimp  = Okt + (size_t)K_N * FF;              // impact [B,D]

    // 4) small dense stage (gather + /4 fused as scale)
    gemm64_kernel<<<B_N / 8, 256>>>(acc_s, student_id, 0.25f, W_stu, b_stu, A1, B_N);
    gemm64_kernel<<<B_N / 8, 256>>>(acc_e, exercise_id, 0.25f, W_exer, b_exer, A2, B_N);
    gemm64_kernel<<<K_N / 8, 256>>>(acc_k, nullptr, 0.25f, W_know, b_know, Okt, K_N);
    disc_kernel<<<B_N / 8, 256>>>(acc_e, exercise_id, W_disc, b_disc, Odisc, B_N);
    impact_kernel<<<B_N * 16 / 256, 256>>>(impact_emb, exercise_id, Oimp);

    // 5) TF32 tensor-core big GEMM pair: O1 = A1 @ Okt^T, O2 = A2 @ Okt^T
    dim3 grid(B_N / 128, (K_N + 63) / 64);
    big_gemm_tf32_dual<<<grid, 256>>>(A1, A2, Okt, O1, O2);
}

// round 3
// speedup vs baseline: 1.5925x; 1.2876x over previous
#include <cuda_runtime.h>
#include <cstdint>
#include <cstddef>

#define S_N 100000
#define E_N 30000
#define K_N 1000
#define DD 64
#define FF 128
#define B_N 16384
#define NNZ_S 1600000
#define NNZ_E 480000
#define NNZ_K 32000
#define NNZ_TOT (NNZ_S + NNZ_E + NNZ_K)
#define MOM 0.9f
#define LEAK_F 0.1f

// scan segmentation (1024-wide blocks)
#define NB_S 98   // ceil(100001/1024)
#define NB_E 30   // ceil(30001/1024)
#define NB_K 1
#define NB_TOT (NB_S + NB_E + NB_K)

static constexpr size_t al256(size_t x) { return (x + 255) & ~(size_t)255; }

// ---------------- static scratch arena ----------------
// rowptrs contiguous so one zero pass covers all three
static constexpr size_t O_RP_S = 0;
static constexpr size_t O_RP_E = O_RP_S + (size_t)(S_N + 1) * 4;
static constexpr size_t O_RP_K = O_RP_E + (size_t)(E_N + 1) * 4;
static constexpr size_t RP_END = O_RP_K + (size_t)(K_N + 1) * 4;
static constexpr int    ZERO_INTS = (int)(RP_END / 4);

static constexpr size_t O_CUR_S = al256(RP_END);
static constexpr size_t O_CUR_E = al256(O_CUR_S + (size_t)S_N * 4);
static constexpr size_t O_CUR_K = al256(O_CUR_E + (size_t)E_N * 4);
static constexpr size_t O_BSUMS = al256(O_CUR_K + (size_t)K_N * 4);
static constexpr size_t O_PAIRS_S = al256(O_BSUMS + 256 * 4);
static constexpr size_t O_PAIRS_E = al256(O_PAIRS_S + (size_t)NNZ_S * 8);
static constexpr size_t O_PAIRS_K = al256(O_PAIRS_E + (size_t)NNZ_E * 8);
static constexpr size_t O_X1_S = al256(O_PAIRS_K + (size_t)NNZ_K * 8);
static constexpr size_t O_X2_S = al256(O_X1_S + (size_t)S_N * DD * 4);
static constexpr size_t O_X3_S = al256(O_X2_S + (size_t)S_N * DD * 4);
static constexpr size_t O_X1_E = al256(O_X3_S + (size_t)S_N * DD * 4);
static constexpr size_t O_X2_E = al256(O_X1_E + (size_t)E_N * DD * 4);
static constexpr size_t O_X3_E = al256(O_X2_E + (size_t)E_N * DD * 4);
static constexpr size_t O_X1_K = al256(O_X3_E + (size_t)E_N * DD * 4);
static constexpr size_t O_X2_K = al256(O_X1_K + (size_t)K_N * DD * 4);
static constexpr size_t O_X3_K = al256(O_X2_K + (size_t)K_N * DD * 4);
static constexpr size_t O_A1   = al256(O_X3_K + (size_t)K_N * DD * 4);
static constexpr size_t O_A2   = al256(O_A1 + (size_t)B_N * FF * 4);
static constexpr size_t ARENA_BYTES = al256(O_A2 + (size_t)B_N * FF * 4);

__device__ __align__(256) unsigned char g_arena[ARENA_BYTES];

// ---------------- CSR build (segmented over 3 graphs) ----------------
__global__ void zero_int_kernel(int* p, int n) {
    int i = blockIdx.x * blockDim.x + threadIdx.x;
    if (i < n) p[i] = 0;
}

__global__ void hist_all_kernel(const int* __restrict__ s_rows, const int* __restrict__ e_rows,
                                const int* __restrict__ k_rows, int* __restrict__ rp_s,
                                int* __restrict__ rp_e, int* __restrict__ rp_k) {
    int i = blockIdx.x * blockDim.x + threadIdx.x;
    if (i < NNZ_S) {
        atomicAdd(&rp_s[__ldg(s_rows + i) + 1], 1);
    } else if (i < NNZ_S + NNZ_E) {
        atomicAdd(&rp_e[__ldg(e_rows + (i - NNZ_S)) + 1], 1);
    } else if (i < NNZ_TOT) {
        atomicAdd(&rp_k[__ldg(k_rows + (i - NNZ_S - NNZ_E)) + 1], 1);
    }
}

// per-block inclusive scan over the 3 concatenated rowptr segments
__global__ void scan_block_all(int* __restrict__ rp_s, int* __restrict__ rp_e,
                               int* __restrict__ rp_k, int* __restrict__ bsums) {
    __shared__ int sh[2048];
    int b = blockIdx.x;
    int* x; int n; int lb;
    if (b < NB_S)            { x = rp_s; n = S_N + 1; lb = b; }
    else if (b < NB_S + NB_E){ x = rp_e; n = E_N + 1; lb = b - NB_S; }
    else                     { x = rp_k; n = K_N + 1; lb = b - NB_S - NB_E; }
    int i = lb * 1024 + threadIdx.x;
    int v = (i < n) ? x[i] : 0;
    sh[threadIdx.x] = v;
    __syncthreads();
    int cur = 0;
    #pragma unroll
    for (int off = 1; off < 1024; off <<= 1) {
        int val = sh[cur * 1024 + threadIdx.x];
        if ((int)threadIdx.x >= off) val += sh[cur * 1024 + threadIdx.x - off];
        sh[(cur ^ 1) * 1024 + threadIdx.x] = val;
        cur ^= 1;
        __syncthreads();
    }
    if (i < n) x[i] = sh[cur * 1024 + threadIdx.x];
    if (threadIdx.x == 1023) bsums[b] = sh[cur * 1024 + 1023];
}

// exclusive scan of block sums, per segment, single block of 128
__global__ void scan_bsums_all(int* __restrict__ bsums) {
    __shared__ int sh[256];
    int t = threadIdx.x;
    int off_seg[3] = {0, NB_S, NB_S + NB_E};
    int cnt_seg[3] = {NB_S, NB_E, NB_K};
    for (int s = 0; s < 3; s++) {
        int v = (t < cnt_seg[s]) ? bsums[off_seg[s] + t] : 0;
        sh[t] = v;
        __syncthreads();
        int cur = 0;
        #pragma unroll
        for (int off = 1; off < 128; off <<= 1) {
            int val = sh[cur * 128 + t];
            if (t >= off) val += sh[cur * 128 + t - off];
            sh[(cur ^ 1) * 128 + t] = val;
            cur ^= 1;
            __syncthreads();
        }
        if (t < cnt_seg[s]) bsums[off_seg[s] + t] = sh[cur * 128 + t] - v;  // exclusive
        __syncthreads();
    }
}

// add block prefix + emit cursor = rowptr[row-start]
__global__ void scan_add_cursor_all(int* __restrict__ rp_s, int* __restrict__ rp_e,
                                    int* __restrict__ rp_k, int* __restrict__ cur_s,
                                    int* __restrict__ cur_e, int* __restrict__ cur_k,
                                    const int* __restrict__ bsums) {
    int b = blockIdx.x;
    int* x; int* c; int n; int lb;
    if (b < NB_S)            { x = rp_s; c = cur_s; n = S_N + 1; lb = b; }
    else if (b < NB_S + NB_E){ x = rp_e; c = cur_e; n = E_N + 1; lb = b - NB_S; }
    else                     { x = rp_k; c = cur_k; n = K_N + 1; lb = b - NB_S - NB_E; }
    int i = lb * 1024 + threadIdx.x;
    if (i < n) {
        int val = x[i] + bsums[b];
        x[i] = val;
        if (i < n - 1) c[i] = val;
    }
}

__global__ void scatter_all_kernel(
    const int* __restrict__ s_rows, const int* __restrict__ s_cols, const float* __restrict__ s_vals,
    const int* __restrict__ e_rows, const int* __restrict__ e_cols, const float* __restrict__ e_vals,
    const int* __restrict__ k_rows, const int* __restrict__ k_cols, const float* __restrict__ k_vals,
    int* __restrict__ cur_s, int* __restrict__ cur_e, int* __restrict__ cur_k,
    int2* __restrict__ pairs_s, int2* __restrict__ pairs_e, int2* __restrict__ pairs_k) {
    int i = blockIdx.x * blockDim.x + threadIdx.x;
    if (i < NNZ_S) {
        int p = atomicAdd(&cur_s[__ldg(s_rows + i)], 1);
        pairs_s[p] = make_int2(__ldg(s_cols + i), __float_as_int(__ldg(s_vals + i)));
    } else if (i < NNZ_S + NNZ_E) {
        int j = i - NNZ_S;
        int p = atomicAdd(&cur_e[__ldg(e_rows + j)], 1);
        pairs_e[p] = make_int2(__ldg(e_cols + j), __float_as_int(__ldg(e_vals + j)));
    } else if (i < NNZ_TOT) {
        int j = i - NNZ_S - NNZ_E;
        int p = atomicAdd(&cur_k[__ldg(k_rows + j)], 1);
        pairs_k[p] = make_int2(__ldg(k_cols + j), __float_as_int(__ldg(k_vals + j)));
    }
}

// ---------------- combined SpMM layer ----------------
// xout = A @ xin + MOM*xin for all three graphs in one launch.
// 16 rows / block, 16 threads / row, float4 per thread, unroll-4.
#define GB_S 6250   // ceil(100000/16)
#define GB_E 1875   // ceil(30000/16)
#define GB_K 63     // ceil(1000/16)

struct SpmmArgs {
    const int* rp[3];
    const int2* pr[3];
    const float4* xin[3];
    float4* xout[3];
    int nrows[3];
};

__global__ void __launch_bounds__(256) spmm_all_kernel(SpmmArgs a) {
    int b = blockIdx.x;
    int seg, lb;
    if (b < GB_S)            { seg = 0; lb = b; }
    else if (b < GB_S + GB_E){ seg = 1; lb = b - GB_S; }
    else                     { seg = 2; lb = b - GB_S - GB_E; }
    int row = lb * 16 + (threadIdx.x >> 4);
    int d4 = threadIdx.x & 15;
    if (row >= a.nrows[seg]) return;
    const int* rowptr = a.rp[seg];
    const int2* pairs = a.pr[seg];
    const float4* xin = a.xin[seg];
    int beg = __ldg(rowptr + row);
    int end = __ldg(rowptr + row + 1);
    float4 s = make_float4(0.f, 0.f, 0.f, 0.f);
    int j = beg;
    for (; j + 3 < end; j += 4) {
        int2 p0 = __ldg(pairs + j);
        int2 p1 = __ldg(pairs + j + 1);
        int2 p2 = __ldg(pairs + j + 2);
        int2 p3 = __ldg(pairs + j + 3);
        float4 v0 = __ldg(xin + ((size_t)p0.x << 4) + d4);
        float4 v1 = __ldg(xin + ((size_t)p1.x << 4) + d4);
        float4 v2 = __ldg(xin + ((size_t)p2.x << 4) + d4);
        float4 v3 = __ldg(xin + ((size_t)p3.x << 4) + d4);
        float w0 = __int_as_float(p0.y), w1 = __int_as_float(p1.y);
        float w2 = __int_as_float(p2.y), w3 = __int_as_float(p3.y);
        s.x = fmaf(w0, v0.x, s.x); s.y = fmaf(w0, v0.y, s.y); s.z = fmaf(w0, v0.z, s.z); s.w = fmaf(w0, v0.w, s.w);
        s.x = fmaf(w1, v1.x, s.x); s.y = fmaf(w1, v1.y, s.y); s.z = fmaf(w1, v1.z, s.z); s.w = fmaf(w1, v1.w, s.w);
        s.x = fmaf(w2, v2.x, s.x); s.y = fmaf(w2, v2.y, s.y); s.z = fmaf(w2, v2.z, s.z); s.w = fmaf(w2, v2.w, s.w);
        s.x = fmaf(w3, v3.x, s.x); s.y = fmaf(w3, v3.y, s.y); s.z = fmaf(w3, v3.z, s.z); s.w = fmaf(w3, v3.w, s.w);
    }
    for (; j < end; j++) {
        int2 p = __ldg(pairs + j);
        float w = __int_as_float(p.y);
        float4 v = __ldg(xin + ((size_t)p.x << 4) + d4);
        s.x = fmaf(w, v.x, s.x); s.y = fmaf(w, v.y, s.y); s.z = fmaf(w, v.z, s.z); s.w = fmaf(w, v.w, s.w);
    }
    size_t o = ((size_t)row << 4) + d4;
    float4 m = xin[o];
    s.x += MOM * m.x; s.y += MOM * m.y; s.z += MOM * m.z; s.w += MOM * m.w;
    a.xout[seg][o] = s;
}

// ---------------- merged dense stage ----------------
__device__ __forceinline__ uint32_t f2tf32(float f) {
    uint32_t u;
    asm("cvt.rna.tf32.f32 %0, %1;" : "=r"(u) : "f"(f));
    return u;
}

#define G_STU 2048
#define G_EXE 2048
#define G_KNO 125
#define G_IMP 1024
#define G_DENSE (G_STU + G_EXE + G_KNO + G_IMP)

struct DenseArgs {
    const float *xs0, *xs1, *xs2, *xs3;
    const float *xe0, *xe1, *xe2, *xe3;
    const float *xk0, *xk1, *xk2, *xk3;
    const int *sid, *eid;
    const float *Ws, *bs, *We, *be, *Wk, *bk, *Wd, *bd;
    const float *imp;
    float *A1, *A2, *Okt, *Odisc, *Oimp;
};

// one block = 8 rows of [gather-sum /4] @ W[64x128] + bias, leaky; optional tf32 store + disc
__device__ void gemm64_body(const float* x0, const float* x1, const float* x2, const float* x3,
                            const int* ids, const float* W, const float* bias, float* out,
                            int rows, int r0, bool tf32_store,
                            bool do_disc, const float* Wd, const float* bd, float* odisc) {
    __shared__ float Ws[64 * 128];
    __shared__ float Xs[8][64];
    int tid = threadIdx.x;
    const float4* W4 = (const float4*)W;
    float4* Ws4 = (float4*)Ws;
    #pragma unroll
    for (int i = 0; i < 8; i++) Ws4[tid + i * 256] = W4[tid + i * 256];
    if (tid < 128) {
        int rr = tid >> 4;
        int c4 = tid & 15;
        int r = r0 + rr;
        float4 v = make_float4(0.f, 0.f, 0.f, 0.f);
        if (r < rows) {
            int rid = ids ? __ldg(ids + r) : r;
            size_t o = ((size_t)rid << 4) + c4;
            float4 a0 = __ldg((const float4*)x0 + o);
            float4 a1 = __ldg((const float4*)x1 + o);
            float4 a2 = __ldg((const float4*)x2 + o);
            float4 a3 = __ldg((const float4*)x3 + o);
            v.x = 0.25f * (a0.x + a1.x + a2.x + a3.x);
            v.y = 0.25f * (a0.y + a1.y + a2.y + a3.y);
            v.z = 0.25f * (a0.z + a1.z + a2.z + a3.z);
            v.w = 0.25f * (a0.w + a1.w + a2.w + a3.w);
        }
        ((float4*)&Xs[rr][0])[c4] = v;
    }
    __syncthreads();
    int col = tid & 127;
    int rbase = tid >> 7;
    float bv = __ldg(bias + col);
    #pragma unroll
    for (int rr = 0; rr < 4; rr++) {
        int lrow = rr * 2 + rbase;
        int r = r0 + lrow;
        if (r >= rows) continue;
        float a = bv;
        #pragma unroll
        for (int i = 0; i < 64; i++) a = fmaf(Xs[lrow][i], Ws[i * 128 + col], a);
        float rv = (a > 0.f) ? a : LEAK_F * a;
        if (tf32_store) ((uint32_t*)out)[(size_t)r * 128 + col] = f2tf32(rv);
        else out[(size_t)r * 128 + col] = rv;
    }
    if (do_disc && tid < 32) {
        int lrow = tid >> 2;       // 8 rows
        int part = tid & 3;        // 4 lanes x 16 elems
        float s = 0.f;
        #pragma unroll
        for (int i = 0; i < 16; i++) s += Xs[lrow][part * 16 + i] * __ldg(Wd + part * 16 + i);
        s += __shfl_xor_sync(0xFFFFFFFFu, s, 1);
        s += __shfl_xor_sync(0xFFFFFFFFu, s, 2);
        if (part == 0) odisc[r0 + lrow] = 1.f / (1.f + __expf(-(s + __ldg(bd))));
    }
}

__global__ void __launch_bounds__(256) dense_all_kernel(DenseArgs a) {
    int b = blockIdx.x;
    if (b < G_STU) {
        gemm64_body(a.xs0, a.xs1, a.xs2, a.xs3, a.sid, a.Ws, a.bs, a.A1, B_N, b * 8,
                    true, false, nullptr, nullptr, nullptr);
    } else if (b < G_STU + G_EXE) {
        gemm64_body(a.xe0, a.xe1, a.xe2, a.xe3, a.eid, a.We, a.be, a.A2, B_N, (b - G_STU) * 8,
                    true, true, a.Wd, a.bd, a.Odisc);
    } else if (b < G_STU + G_EXE + G_KNO) {
        gemm64_body(a.xk0, a.xk1, a.xk2, a.xk3, nullptr, a.Wk, a.bk, a.Okt, K_N,
                    (b - G_STU - G_EXE) * 8, false, false, nullptr, nullptr, nullptr);
    } else {
        int t = (b - G_STU - G_EXE - G_KNO) * 256 + threadIdx.x;   // B_N*16 threads
        int bi = t >> 4, q = t & 15;
        ((float4*)a.Oimp)[((size_t)bi << 4) + q] =
            __ldg((const float4*)a.imp + ((size_t)__ldg(a.eid + bi) << 4) + q);
    }
}

// ---------------- TF32 tensor-core big GEMM ----------------
// O1 = A1 @ Bt^T, O2 = A2 @ Bt^T. A1/A2 are stored as tf32 bit patterns.
#define MMA_TF32(d, a, b)                                                     \
    asm volatile(                                                             \
        "mma.sync.aligned.m16n8k8.row.col.f32.tf32.tf32.f32 "                 \
        "{%0,%1,%2,%3}, {%4,%5,%6,%7}, {%8,%9}, {%0,%1,%2,%3};\n"             \
        : "+f"(d[0]), "+f"(d[1]), "+f"(d[2]), "+f"(d[3])                      \
        : "r"(a[0]), "r"(a[1]), "r"(a[2]), "r"(a[3]), "r"(b[0]), "r"(b[1]))

#define SMPAD 36

__global__ void __launch_bounds__(256) big_gemm_tf32_dual(
    const uint32_t* __restrict__ A1, const uint32_t* __restrict__ A2,
    const float* __restrict__ Bt, float* __restrict__ O1, float* __restrict__ O2) {
    __shared__ uint32_t As1[128 * SMPAD];
    __shared__ uint32_t As2[128 * SMPAD];
    __shared__ uint32_t Bs[64 * SMPAD];

    int tid = threadIdx.x;
    int warp = tid >> 5;
    int lane = tid & 31;
    int g = lane >> 2;
    int tg = lane & 3;
    int wm = warp & 3;
    int wn = warp >> 2;
    int m0 = blockIdx.x * 128;
    int n0 = blockIdx.y * 64;

    float acc1[2][4][4] = {};
    float acc2[2][4][4] = {};

    for (int kc = 0; kc < 128; kc += 32) {
        #pragma unroll
        for (int i = 0; i < 4; i++) {
            int idx = tid + i * 256;
            int row = idx >> 3, q = idx & 7;
            uint4 v1 = *(const uint4*)(A1 + (size_t)(m0 + row) * 128 + kc + q * 4);
            uint4 v2 = *(const uint4*)(A2 + (size_t)(m0 + row) * 128 + kc + q * 4);
            uint32_t* p1 = &As1[row * SMPAD + q * 4];
            uint32_t* p2 = &As2[row * SMPAD + q * 4];
            p1[0] = v1.x; p1[1] = v1.y; p1[2] = v1.z; p1[3] = v1.w;
            p2[0] = v2.x; p2[1] = v2.y; p2[2] = v2.z; p2[3] = v2.w;
        }
        #pragma unroll
        for (int i = 0; i < 2; i++) {
            int idx = tid + i * 256;
            int row = idx >> 3, q = idx & 7;
            float4 v = make_float4(0.f, 0.f, 0.f, 0.f);
            if (n0 + row < K_N) v = *(const float4*)(Bt + (size_t)(n0 + row) * 128 + kc + q * 4);
            uint32_t* p = &Bs[row * SMPAD + q * 4];
            p[0] = f2tf32(v.x); p[1] = f2tf32(v.y); p[2] = f2tf32(v.z); p[3] = f2tf32(v.w);
        }
        __syncthreads();

        #pragma unroll
        for (int ks = 0; ks < 4; ks++) {
            int k0 = ks * 8;
            uint32_t b[4][2];
            #pragma unroll
            for (int nt = 0; nt < 4; nt++) {
                const uint32_t* bp = &Bs[(wn * 32 + nt * 8 + g) * SMPAD + k0 + tg];
                b[nt][0] = bp[0];
                b[nt][1] = bp[4];
            }
            #pragma unroll
            for (int mt = 0; mt < 2; mt++) {
                uint32_t a[4];
                const uint32_t* ap0 = &As1[(wm * 32 + mt * 16 + g) * SMPAD + k0 + tg];
                a[0] = ap0[0];
                a[1] = ap0[8 * SMPAD];
                a[2] = ap0[4];
                a[3] = ap0[8 * SMPAD + 4];
                #pragma unroll
                for (int nt = 0; nt < 4; nt++) MMA_TF32(acc1[mt][nt], a, b[nt]);
                const uint32_t* ap1 = &As2[(wm * 32 + mt * 16 + g) * SMPAD + k0 + tg];
                a[0] = ap1[0];
                a[1] = ap1[8 * SMPAD];
                a[2] = ap1[4];
                a[3] = ap1[8 * SMPAD + 4];
                #pragma unroll
                for (int nt = 0; nt < 4; nt++) MMA_TF32(acc2[mt][nt], a, b[nt]);
            }
        }
        __syncthreads();
    }

    #pragma unroll
    for (int mt = 0; mt < 2; mt++) {
        #pragma unroll
        for (int nt = 0; nt < 4; nt++) {
            int col = n0 + wn * 32 + nt * 8 + tg * 2;
            if (col >= K_N) continue;
            size_t r0 = (size_t)(m0 + wm * 32 + mt * 16 + g);
            size_t r1 = r0 + 8;
            *(float2*)(O1 + r0 * K_N + col) = make_float2(acc1[mt][nt][0], acc1[mt][nt][1]);
            *(float2*)(O1 + r1 * K_N + col) = make_float2(acc1[mt][nt][2], acc1[mt][nt][3]);
            *(float2*)(O2 + r0 * K_N + col) = make_float2(acc2[mt][nt][0], acc2[mt][nt][1]);
            *(float2*)(O2 + r1 * K_N + col) = make_float2(acc2[mt][nt][2], acc2[mt][nt][3]);
        }
    }
}

// ---------------- host orchestration ----------------
extern "C" void kernel_launch(void* const* d_in, const int* in_sizes, int n_in,
                              void* d_out, int out_size) {
    (void)in_sizes; (void)n_in; (void)out_size;
    const int*   student_id  = (const int*)d_in[0];
    const int*   exercise_id = (const int*)d_in[1];
    const float* stu_emb     = (const float*)d_in[3];
    const float* exer_emb    = (const float*)d_in[4];
    const float* know_emb    = (const float*)d_in[5];
    const float* impact_emb  = (const float*)d_in[6];
    const int*   s_rows = (const int*)d_in[7];
    const int*   s_cols = (const int*)d_in[8];
    const float* s_vals = (const float*)d_in[9];
    const int*   e_rows = (const int*)d_in[10];
    const int*   e_cols = (const int*)d_in[11];
    const float* e_vals = (const float*)d_in[12];
    const int*   k_rows = (const int*)d_in[13];
    const int*   k_cols = (const int*)d_in[14];
    const float* k_vals = (const float*)d_in[15];
    const float* W_stu  = (const float*)d_in[16];
    const float* b_stu  = (const float*)d_in[17];
    const float* W_exer = (const float*)d_in[18];
    const float* b_exer = (const float*)d_in[19];
    const float* W_know = (const float*)d_in[20];
    const float* b_know = (const float*)d_in[21];
    const float* W_disc = (const float*)d_in[22];
    const float* b_disc = (const float*)d_in[23];

    unsigned char* A = nullptr;
    cudaGetSymbolAddress((void**)&A, g_arena);

    int*  rp_s  = (int*)(A + O_RP_S);
    int*  rp_e  = (int*)(A + O_RP_E);
    int*  rp_k  = (int*)(A + O_RP_K);
    int*  cur_s = (int*)(A + O_CUR_S);
    int*  cur_e = (int*)(A + O_CUR_E);
    int*  cur_k = (int*)(A + O_CUR_K);
    int*  bsums = (int*)(A + O_BSUMS);
    int2* pairs_s = (int2*)(A + O_PAIRS_S);
    int2* pairs_e = (int2*)(A + O_PAIRS_E);
    int2* pairs_k = (int2*)(A + O_PAIRS_K);
    float* x1_s = (float*)(A + O_X1_S);
    float* x2_s = (float*)(A + O_X2_S);
    float* x3_s = (float*)(A + O_X3_S);
    float* x1_e = (float*)(A + O_X1_E);
    float* x2_e = (float*)(A + O_X2_E);
    float* x3_e = (float*)(A + O_X3_E);
    float* x1_k = (float*)(A + O_X1_K);
    float* x2_k = (float*)(A + O_X2_K);
    float* x3_k = (float*)(A + O_X3_K);
    float* A1   = (float*)(A + O_A1);
    float* A2   = (float*)(A + O_A2);

    // 1) CSR build (6 launches total)
    zero_int_kernel<<<(ZERO_INTS + 1023) / 1024, 1024>>>(rp_s, ZERO_INTS);
    hist_all_kernel<<<(NNZ_TOT + 255) / 256, 256>>>(s_rows, e_rows, k_rows, rp_s, rp_e, rp_k);
    scan_block_all<<<NB_TOT, 1024>>>(rp_s, rp_e, rp_k, bsums);
    scan_bsums_all<<<1, 128>>>(bsums);
    scan_add_cursor_all<<<NB_TOT, 1024>>>(rp_s, rp_e, rp_k, cur_s, cur_e, cur_k, bsums);
    scatter_all_kernel<<<(NNZ_TOT + 255) / 256, 256>>>(
        s_rows, s_cols, s_vals, e_rows, e_cols, e_vals, k_rows, k_cols, k_vals,
        cur_s, cur_e, cur_k, pairs_s, pairs_e, pairs_k);

    // 2) 3 combined SpMM layers (lazy accumulation: write x_{l+1} only)
    const float* in_s[4] = {stu_emb, x1_s, x2_s, x3_s};
    const float* in_e[4] = {exer_emb, x1_e, x2_e, x3_e};
    const float* in_k[4] = {know_emb, x1_k, x2_k, x3_k};
    for (int l = 0; l < 3; l++) {
        SpmmArgs sa;
        sa.rp[0] = rp_s;  sa.rp[1] = rp_e;  sa.rp[2] = rp_k;
        sa.pr[0] = pairs_s; sa.pr[1] = pairs_e; sa.pr[2] = pairs_k;
        sa.xin[0] = (const float4*)in_s[l]; sa.xin[1] = (const float4*)in_e[l]; sa.xin[2] = (const float4*)in_k[l];
        sa.xout[0] = (float4*)in_s[l + 1];  sa.xout[1] = (float4*)in_e[l + 1];  sa.xout[2] = (float4*)in_k[l + 1];
        sa.nrows[0] = S_N; sa.nrows[1] = E_N; sa.nrows[2] = K_N;
        spmm_all_kernel<<<GB_S + GB_E + GB_K, 256>>>(sa);
    }

    // 3) output layout
    float* out   = (float*)d_out;
    float* O1    = out;
    float* O2    = O1 + (size_t)B_N * K_N;
    float* Odisc = O2 + (size_t)B_N * K_N;
    float* Okt   = Odisc + B_N;
    float* Oimp  = Okt + (size_t)K_N * FF;

    // 4) merged dense stage (1 launch)
    DenseArgs da;
    da.xs0 = stu_emb; da.xs1 = x1_s; da.xs2 = x2_s; da.xs3 = x3_s;
    da.xe0 = exer_emb; da.xe1 = x1_e; da.xe2 = x2_e; da.xe3 = x3_e;
    da.xk0 = know_emb; da.xk1 = x1_k; da.xk2 = x2_k; da.xk3 = x3_k;
    da.sid = student_id; da.eid = exercise_id;
    da.Ws = W_stu; da.bs = b_stu; da.We = W_exer; da.be = b_exer;
    da.Wk = W_know; da.bk = b_know; da.Wd = W_disc; da.bd = b_disc;
    da.imp = impact_emb;
    da.A1 = A1; da.A2 = A2; da.Okt = Okt; da.Odisc = Odisc; da.Oimp = Oimp;
    dense_all_kernel<<<G_DENSE, 256>>>(da);

    // 5) TF32 big GEMM pair
    dim3 grid(B_N / 128, (K_N + 63) / 64);
    big_gemm_tf32_dual<<<grid, 256>>>((const uint32_t*)A1, (const uint32_t*)A2, Okt, O1, O2);
}

// round 4
// speedup vs baseline: 1.8533x; 1.1638x over previous
#include <cuda_runtime.h>
#include <cstdint>
#include <cstddef>

#define S_N 100000
#define E_N 30000
#define K_N 1000
#define DD 64
#define FF 128
#define B_N 16384
#define NNZ_S 1600000
#define NNZ_E 480000
#define NNZ_K 32000
#define NNZ_TOT (NNZ_S + NNZ_E + NNZ_K)
#define MOM 0.9f
#define LEAK_F 0.1f

// scan segmentation (1024-wide blocks)
#define NB_S 98
#define NB_E 30
#define NB_K 1
#define NB_TOT (NB_S + NB_E + NB_K)

static constexpr size_t al256(size_t x) { return (x + 255) & ~(size_t)255; }

// ---------------- static scratch arena ----------------
static constexpr size_t O_RP_S = 0;
static constexpr size_t O_RP_E = O_RP_S + (size_t)(S_N + 1) * 4;
static constexpr size_t O_RP_K = O_RP_E + (size_t)(E_N + 1) * 4;
static constexpr size_t RP_END = O_RP_K + (size_t)(K_N + 1) * 4;
static constexpr int    ZERO_INTS = (int)(RP_END / 4);

static constexpr size_t O_CUR_S = al256(RP_END);
static constexpr size_t O_CUR_E = al256(O_CUR_S + (size_t)S_N * 4);
static constexpr size_t O_CUR_K = al256(O_CUR_E + (size_t)E_N * 4);
static constexpr size_t O_BSUMS = al256(O_CUR_K + (size_t)K_N * 4);
static constexpr size_t O_PAIRS_S = al256(O_BSUMS + 256 * 4);
static constexpr size_t O_PAIRS_E = al256(O_PAIRS_S + (size_t)NNZ_S * 8);
static constexpr size_t O_PAIRS_K = al256(O_PAIRS_E + (size_t)NNZ_E * 8);
static constexpr size_t O_X1_S = al256(O_PAIRS_K + (size_t)NNZ_K * 8);
static constexpr size_t O_X2_S = al256(O_X1_S + (size_t)S_N * DD * 4);
static constexpr size_t O_X1_E = al256(O_X2_S + (size_t)S_N * DD * 4);
static constexpr size_t O_X2_E = al256(O_X1_E + (size_t)E_N * DD * 4);
static constexpr size_t O_X1_K = al256(O_X2_E + (size_t)E_N * DD * 4);
static constexpr size_t O_X2_K = al256(O_X1_K + (size_t)K_N * DD * 4);
static constexpr size_t O_X3_K = al256(O_X2_K + (size_t)K_N * DD * 4);
static constexpr size_t O_XG_S = al256(O_X3_K + (size_t)K_N * DD * 4);
static constexpr size_t O_XG_E = al256(O_XG_S + (size_t)B_N * DD * 4);
static constexpr size_t O_A1   = al256(O_XG_E + (size_t)B_N * DD * 4);
static constexpr size_t O_A2   = al256(O_A1 + (size_t)B_N * FF * 4);
static constexpr size_t O_BT32 = al256(O_A2 + (size_t)B_N * FF * 4);   // 1024 x 128 tf32
static constexpr size_t ARENA_BYTES = al256(O_BT32 + (size_t)1024 * FF * 4);

__device__ __align__(256) unsigned char g_arena[ARENA_BYTES];

// ---------------- CSR build ----------------
__global__ void zero_int_kernel(int* p, int n) {
    int i = blockIdx.x * blockDim.x + threadIdx.x;
    if (i < n) p[i] = 0;
}

__global__ void hist_all_kernel(const int* __restrict__ s_rows, const int* __restrict__ e_rows,
                                const int* __restrict__ k_rows, int* __restrict__ rp_s,
                                int* __restrict__ rp_e, int* __restrict__ rp_k) {
    int i = blockIdx.x * blockDim.x + threadIdx.x;
    if (i < NNZ_S) {
        atomicAdd(&rp_s[__ldg(s_rows + i) + 1], 1);
    } else if (i < NNZ_S + NNZ_E) {
        atomicAdd(&rp_e[__ldg(e_rows + (i - NNZ_S)) + 1], 1);
    } else if (i < NNZ_TOT) {
        atomicAdd(&rp_k[__ldg(k_rows + (i - NNZ_S - NNZ_E)) + 1], 1);
    }
}

__global__ void scan_block_all(int* __restrict__ rp_s, int* __restrict__ rp_e,
                               int* __restrict__ rp_k, int* __restrict__ bsums) {
    __shared__ int sh[2048];
    int b = blockIdx.x;
    int* x; int n; int lb;
    if (b < NB_S)            { x = rp_s; n = S_N + 1; lb = b; }
    else if (b < NB_S + NB_E){ x = rp_e; n = E_N + 1; lb = b - NB_S; }
    else                     { x = rp_k; n = K_N + 1; lb = b - NB_S - NB_E; }
    int i = lb * 1024 + threadIdx.x;
    int v = (i < n) ? x[i] : 0;
    sh[threadIdx.x] = v;
    __syncthreads();
    int cur = 0;
    #pragma unroll
    for (int off = 1; off < 1024; off <<= 1) {
        int val = sh[cur * 1024 + threadIdx.x];
        if ((int)threadIdx.x >= off) val += sh[cur * 1024 + threadIdx.x - off];
        sh[(cur ^ 1) * 1024 + threadIdx.x] = val;
        cur ^= 1;
        __syncthreads();
    }
    if (i < n) x[i] = sh[cur * 1024 + threadIdx.x];
    if (threadIdx.x == 1023) bsums[b] = sh[cur * 1024 + 1023];
}

__global__ void scan_bsums_all(int* __restrict__ bsums) {
    __shared__ int sh[256];
    int t = threadIdx.x;
    int off_seg[3] = {0, NB_S, NB_S + NB_E};
    int cnt_seg[3] = {NB_S, NB_E, NB_K};
    for (int s = 0; s < 3; s++) {
        int v = (t < cnt_seg[s]) ? bsums[off_seg[s] + t] : 0;
        sh[t] = v;
        __syncthreads();
        int cur = 0;
        #pragma unroll
        for (int off = 1; off < 128; off <<= 1) {
            int val = sh[cur * 128 + t];
            if (t >= off) val += sh[cur * 128 + t - off];
            sh[(cur ^ 1) * 128 + t] = val;
            cur ^= 1;
            __syncthreads();
        }
        if (t < cnt_seg[s]) bsums[off_seg[s] + t] = sh[cur * 128 + t] - v;
        __syncthreads();
    }
}

__global__ void scan_add_cursor_all(int* __restrict__ rp_s, int* __restrict__ rp_e,
                                    int* __restrict__ rp_k, int* __restrict__ cur_s,
                                    int* __restrict__ cur_e, int* __restrict__ cur_k,
                                    const int* __restrict__ bsums) {
    int b = blockIdx.x;
    int* x; int* c; int n; int lb;
    if (b < NB_S)            { x = rp_s; c = cur_s; n = S_N + 1; lb = b; }
    else if (b < NB_S + NB_E){ x = rp_e; c = cur_e; n = E_N + 1; lb = b - NB_S; }
    else                     { x = rp_k; c = cur_k; n = K_N + 1; lb = b - NB_S - NB_E; }
    int i = lb * 1024 + threadIdx.x;
    if (i < n) {
        int val = x[i] + bsums[b];
        x[i] = val;
        if (i < n - 1) c[i] = val;
    }
}

__global__ void scatter_all_kernel(
    const int* __restrict__ s_rows, const int* __restrict__ s_cols, const float* __restrict__ s_vals,
    const int* __restrict__ e_rows, const int* __restrict__ e_cols, const float* __restrict__ e_vals,
    const int* __restrict__ k_rows, const int* __restrict__ k_cols, const float* __restrict__ k_vals,
    int* __restrict__ cur_s, int* __restrict__ cur_e, int* __restrict__ cur_k,
    int2* __restrict__ pairs_s, int2* __restrict__ pairs_e, int2* __restrict__ pairs_k) {
    int i = blockIdx.x * blockDim.x + threadIdx.x;
    if (i < NNZ_S) {
        int p = atomicAdd(&cur_s[__ldg(s_rows + i)], 1);
        pairs_s[p] = make_int2(__ldg(s_cols + i), __float_as_int(__ldg(s_vals + i)));
    } else if (i < NNZ_S + NNZ_E) {
        int j = i - NNZ_S;
        int p = atomicAdd(&cur_e[__ldg(e_rows + j)], 1);
        pairs_e[p] = make_int2(__ldg(e_cols + j), __float_as_int(__ldg(e_vals + j)));
    } else if (i < NNZ_TOT) {
        int j = i - NNZ_S - NNZ_E;
        int p = atomicAdd(&cur_k[__ldg(k_rows + j)], 1);
        pairs_k[p] = make_int2(__ldg(k_cols + j), __float_as_int(__ldg(k_vals + j)));
    }
}

// ---------------- SpMM core ----------------
__device__ __forceinline__ float4 spmm_row(const int* rowptr, const int2* pairs,
                                           const float4* xin, int row, int d4) {
    int beg = __ldg(rowptr + row);
    int end = __ldg(rowptr + row + 1);
    float4 s = make_float4(0.f, 0.f, 0.f, 0.f);
    int j = beg;
    for (; j + 3 < end; j += 4) {
        int2 p0 = __ldg(pairs + j);
        int2 p1 = __ldg(pairs + j + 1);
        int2 p2 = __ldg(pairs + j + 2);
        int2 p3 = __ldg(pairs + j + 3);
        float4 v0 = __ldg(xin + ((size_t)p0.x << 4) + d4);
        float4 v1 = __ldg(xin + ((size_t)p1.x << 4) + d4);
        float4 v2 = __ldg(xin + ((size_t)p2.x << 4) + d4);
        float4 v3 = __ldg(xin + ((size_t)p3.x << 4) + d4);
        float w0 = __int_as_float(p0.y), w1 = __int_as_float(p1.y);
        float w2 = __int_as_float(p2.y), w3 = __int_as_float(p3.y);
        s.x = fmaf(w0, v0.x, s.x); s.y = fmaf(w0, v0.y, s.y); s.z = fmaf(w0, v0.z, s.z); s.w = fmaf(w0, v0.w, s.w);
        s.x = fmaf(w1, v1.x, s.x); s.y = fmaf(w1, v1.y, s.y); s.z = fmaf(w1, v1.z, s.z); s.w = fmaf(w1, v1.w, s.w);
        s.x = fmaf(w2, v2.x, s.x); s.y = fmaf(w2, v2.y, s.y); s.z = fmaf(w2, v2.z, s.z); s.w = fmaf(w2, v2.w, s.w);
        s.x = fmaf(w3, v3.x, s.x); s.y = fmaf(w3, v3.y, s.y); s.z = fmaf(w3, v3.z, s.z); s.w = fmaf(w3, v3.w, s.w);
    }
    for (; j < end; j++) {
        int2 p = __ldg(pairs + j);
        float w = __int_as_float(p.y);
        float4 v = __ldg(xin + ((size_t)p.x << 4) + d4);
        s.x = fmaf(w, v.x, s.x); s.y = fmaf(w, v.y, s.y); s.z = fmaf(w, v.z, s.z); s.w = fmaf(w, v.w, s.w);
    }
    return s;
}

#define GB_S 6250
#define GB_E 1875
#define GB_K 63

struct SpmmArgs {
    const int* rp[3];
    const int2* pr[3];
    const float4* xin[3];
    float4* xout[3];
    int nrows[3];
};

__global__ void __launch_bounds__(256) spmm_all_kernel(SpmmArgs a) {
    int b = blockIdx.x;
    int seg, lb;
    if (b < GB_S)            { seg = 0; lb = b; }
    else if (b < GB_S + GB_E){ seg = 1; lb = b - GB_S; }
    else                     { seg = 2; lb = b - GB_S - GB_E; }
    int row = lb * 16 + (threadIdx.x >> 4);
    int d4 = threadIdx.x & 15;
    if (row >= a.nrows[seg]) return;
    const float4* xin = a.xin[seg];
    float4 s = spmm_row(a.rp[seg], a.pr[seg], xin, row, d4);
    size_t o = ((size_t)row << 4) + d4;
    float4 m = xin[o];
    s.x += MOM * m.x; s.y += MOM * m.y; s.z += MOM * m.z; s.w += MOM * m.w;
    a.xout[seg][o] = s;
}

// Layer 3: stu & exer restricted to batch indices (compact outputs), know full.
#define GL_S 1024   // B_N/16
#define GL_E 1024
#define GL_K 63

struct Spmm3Args {
    const int* rp_s; const int2* pr_s; const float4* x2_s; float4* xg_s; const int* sid;
    const int* rp_e; const int2* pr_e; const float4* x2_e; float4* xg_e; const int* eid;
    const int* rp_k; const int2* pr_k; const float4* x2_k; float4* x3_k;
};

__global__ void __launch_bounds__(256) spmm_l3_kernel(Spmm3Args a) {
    int b = blockIdx.x;
    int d4 = threadIdx.x & 15;
    int lr = (threadIdx.x >> 4);
    if (b < GL_S) {
        int r = b * 16 + lr;
        int row = __ldg(a.sid + r);
        float4 s = spmm_row(a.rp_s, a.pr_s, a.x2_s, row, d4);
        float4 m = a.x2_s[((size_t)row << 4) + d4];
        s.x += MOM * m.x; s.y += MOM * m.y; s.z += MOM * m.z; s.w += MOM * m.w;
        a.xg_s[((size_t)r << 4) + d4] = s;
    } else if (b < GL_S + GL_E) {
        int r = (b - GL_S) * 16 + lr;
        int row = __ldg(a.eid + r);
        float4 s = spmm_row(a.rp_e, a.pr_e, a.x2_e, row, d4);
        float4 m = a.x2_e[((size_t)row << 4) + d4];
        s.x += MOM * m.x; s.y += MOM * m.y; s.z += MOM * m.z; s.w += MOM * m.w;
        a.xg_e[((size_t)r << 4) + d4] = s;
    } else {
        int row = (b - GL_S - GL_E) * 16 + lr;
        if (row >= K_N) return;
        float4 s = spmm_row(a.rp_k, a.pr_k, a.x2_k, row, d4);
        float4 m = a.x2_k[((size_t)row << 4) + d4];
        s.x += MOM * m.x; s.y += MOM * m.y; s.z += MOM * m.z; s.w += MOM * m.w;
        a.x3_k[((size_t)row << 4) + d4] = s;
    }
}

// ---------------- merged dense stage ----------------
__device__ __forceinline__ uint32_t f2tf32(float f) {
    uint32_t u;
    asm("cvt.rna.tf32.f32 %0, %1;" : "=r"(u) : "f"(f));
    return u;
}

#define G_STU 2048
#define G_EXE 2048
#define G_KNO 125
#define G_PAD 1
#define G_IMP 1024
#define G_DENSE (G_STU + G_EXE + G_KNO + G_PAD + G_IMP)

struct DenseArgs {
    const float *xs0, *xs1, *xs2, *xs3;   // xs3 compact (indexed by batch row)
    const float *xe0, *xe1, *xe2, *xe3;   // xe3 compact
    const float *xk0, *xk1, *xk2, *xk3;
    const int *sid, *eid;
    const float *Ws, *bs, *We, *be, *Wk, *bk, *Wd, *bd;
    const float *imp;
    float *A1, *A2, *Okt, *Odisc, *Oimp;
    uint32_t *Bt32;
};

__device__ void gemm64_body(const float* x0, const float* x1, const float* x2, const float* x3,
                            bool x3_direct, const int* ids, const float* W, const float* bias,
                            float* out, uint32_t* out_tf32, int rows, int r0, bool a_tf32,
                            bool do_disc, const float* Wd, const float* bd, float* odisc) {
    __shared__ float Ws[64 * 128];
    __shared__ float Xs[8][64];
    int tid = threadIdx.x;
    const float4* W4 = (const float4*)W;
    float4* Ws4 = (float4*)Ws;
    #pragma unroll
    for (int i = 0; i < 8; i++) Ws4[tid + i * 256] = W4[tid + i * 256];
    if (tid < 128) {
        int rr = tid >> 4;
        int c4 = tid & 15;
        int r = r0 + rr;
        float4 v = make_float4(0.f, 0.f, 0.f, 0.f);
        if (r < rows) {
            int rid = ids ? __ldg(ids + r) : r;
            size_t o = ((size_t)rid << 4) + c4;
            size_t o3 = x3_direct ? (((size_t)r << 4) + c4) : o;
            float4 a0 = __ldg((const float4*)x0 + o);
            float4 a1 = __ldg((const float4*)x1 + o);
            float4 a2 = __ldg((const float4*)x2 + o);
            float4 a3 = __ldg((const float4*)x3 + o3);
            v.x = 0.25f * (a0.x + a1.x + a2.x + a3.x);
            v.y = 0.25f * (a0.y + a1.y + a2.y + a3.y);
            v.z = 0.25f * (a0.z + a1.z + a2.z + a3.z);
            v.w = 0.25f * (a0.w + a1.w + a2.w + a3.w);
        }
        ((float4*)&Xs[rr][0])[c4] = v;
    }
    __syncthreads();
    int col = tid & 127;
    int rbase = tid >> 7;
    float bv = __ldg(bias + col);
    #pragma unroll
    for (int rr = 0; rr < 4; rr++) {
        int lrow = rr * 2 + rbase;
        int r = r0 + lrow;
        if (r >= rows) continue;
        float a = bv;
        #pragma unroll
        for (int i = 0; i < 64; i++) a = fmaf(Xs[lrow][i], Ws[i * 128 + col], a);
        float rv = (a > 0.f) ? a : LEAK_F * a;
        if (a_tf32) ((uint32_t*)out)[(size_t)r * 128 + col] = f2tf32(rv);
        else        out[(size_t)r * 128 + col] = rv;
        if (out_tf32) out_tf32[(size_t)r * 128 + col] = f2tf32(rv);
    }
    if (do_disc && tid < 32) {
        int lrow = tid >> 2;
        int part = tid & 3;
        float s = 0.f;
        #pragma unroll
        for (int i = 0; i < 16; i++) s += Xs[lrow][part * 16 + i] * __ldg(Wd + part * 16 + i);
        s += __shfl_xor_sync(0xFFFFFFFFu, s, 1);
        s += __shfl_xor_sync(0xFFFFFFFFu, s, 2);
        if (part == 0) odisc[r0 + lrow] = 1.f / (1.f + __expf(-(s + __ldg(bd))));
    }
}

__global__ void __launch_bounds__(256) dense_all_kernel(DenseArgs a) {
    int b = blockIdx.x;
    if (b < G_STU) {
        gemm64_body(a.xs0, a.xs1, a.xs2, a.xs3, true, a.sid, a.Ws, a.bs, a.A1, nullptr,
                    B_N, b * 8, true, false, nullptr, nullptr, nullptr);
    } else if (b < G_STU + G_EXE) {
        gemm64_body(a.xe0, a.xe1, a.xe2, a.xe3, true, a.eid, a.We, a.be, a.A2, nullptr,
                    B_N, (b - G_STU) * 8, true, true, a.Wd, a.bd, a.Odisc);
    } else if (b < G_STU + G_EXE + G_KNO) {
        gemm64_body(a.xk0, a.xk1, a.xk2, a.xk3, false, nullptr, a.Wk, a.bk, a.Okt, a.Bt32,
                    K_N, (b - G_STU - G_EXE) * 8, false, false, nullptr, nullptr, nullptr);
    } else if (b < G_STU + G_EXE + G_KNO + G_PAD) {
        // zero tf32-B pad rows [1000,1024): 24*128 = 3072 words
        for (int i = threadIdx.x; i < 24 * 128; i += 256)
            a.Bt32[(size_t)K_N * 128 + i] = 0u;
    } else {
        int t = (b - G_STU - G_EXE - G_KNO - G_PAD) * 256 + threadIdx.x;
        int bi = t >> 4, q = t & 15;
        ((float4*)a.Oimp)[((size_t)bi << 4) + q] =
            __ldg((const float4*)a.imp + ((size_t)__ldg(a.eid + bi) << 4) + q);
    }
}

// ---------------- TF32 tensor-core big GEMM (128x128 tile, cp.async 2-stage) ----------------
#define MMA_TF32(d, a, b)                                                     \
    asm volatile(                                                             \
        "mma.sync.aligned.m16n8k8.row.col.f32.tf32.tf32.f32 "                 \
        "{%0,%1,%2,%3}, {%4,%5,%6,%7}, {%8,%9}, {%0,%1,%2,%3};\n"             \
        : "+f"(d[0]), "+f"(d[1]), "+f"(d[2]), "+f"(d[3])                      \
        : "r"(a[0]), "r"(a[1]), "r"(a[2]), "r"(a[3]), "r"(b[0]), "r"(b[1]))

#define SMPAD 36
#define STAGE_W (3 * 128 * SMPAD)              // words per stage
#define GEMM_SMEM_BYTES (2 * STAGE_W * 4)      // 110,592

__device__ __forceinline__ void cp16(uint32_t dst, const void* src) {
    asm volatile("cp.async.cg.shared.global [%0], [%1], 16;" :: "r"(dst), "l"(src));
}

__device__ __forceinline__ void load_stage(uint32_t sbase, const uint32_t* A1, const uint32_t* A2,
                                           const uint32_t* B32, int m0, int n0, int kc, int tid) {
    #pragma unroll
    for (int i = 0; i < 4; i++) {
        int idx = tid + i * 256;            // 0..1023
        int row = idx >> 3, q = idx & 7;
        uint32_t off = (uint32_t)(row * SMPAD + q * 4) * 4;
        cp16(sbase + off,                          A1 + (size_t)(m0 + row) * 128 + kc + q * 4);
        cp16(sbase + 128 * SMPAD * 4 + off,        A2 + (size_t)(m0 + row) * 128 + kc + q * 4);
        cp16(sbase + 2 * 128 * SMPAD * 4 + off,    B32 + (size_t)(n0 + row) * 128 + kc + q * 4);
    }
    asm volatile("cp.async.commit_group;");
}

__global__ void __launch_bounds__(256, 1) big_gemm_tf32_dual(
    const uint32_t* __restrict__ A1, const uint32_t* __restrict__ A2,
    const uint32_t* __restrict__ B32, float* __restrict__ O1, float* __restrict__ O2) {
    extern __shared__ uint32_t sm[];
    uint32_t sbase = (uint32_t)__cvta_generic_to_shared(sm);

    int tid = threadIdx.x;
    int warp = tid >> 5;
    int lane = tid & 31;
    int g = lane >> 2;
    int tg = lane & 3;
    int wm = warp >> 1;      // 0..3 -> 32 rows each
    int wn = warp & 1;       // 0..1 -> 64 cols each
    int m0 = blockIdx.x * 128;
    int n0 = blockIdx.y * 128;

    float acc1[2][8][4] = {};
    float acc2[2][8][4] = {};

    load_stage(sbase, A1, A2, B32, m0, n0, 0, tid);

    #pragma unroll
    for (int c = 0; c < 4; c++) {
        if (c < 3) {
            load_stage(sbase + ((c + 1) & 1) * STAGE_W * 4, A1, A2, B32, m0, n0, (c + 1) * 32, tid);
            asm volatile("cp.async.wait_group 1;");
        } else {
            asm volatile("cp.async.wait_group 0;");
        }
        __syncthreads();
        const uint32_t* As1 = sm + (c & 1) * STAGE_W;
        const uint32_t* As2 = As1 + 128 * SMPAD;
        const uint32_t* Bs  = As2 + 128 * SMPAD;

        #pragma unroll
        for (int ks = 0; ks < 4; ks++) {
            int k0 = ks * 8;
            uint32_t b[8][2];
            #pragma unroll
            for (int nt = 0; nt < 8; nt++) {
                const uint32_t* bp = &Bs[(wn * 64 + nt * 8 + g) * SMPAD + k0 + tg];
                b[nt][0] = bp[0];
                b[nt][1] = bp[4];
            }
            #pragma unroll
            for (int mt = 0; mt < 2; mt++) {
                uint32_t a[4];
                const uint32_t* ap = &As1[(wm * 32 + mt * 16 + g) * SMPAD + k0 + tg];
                a[0] = ap[0]; a[1] = ap[8 * SMPAD]; a[2] = ap[4]; a[3] = ap[8 * SMPAD + 4];
                #pragma unroll
                for (int nt = 0; nt < 8; nt++) MMA_TF32(acc1[mt][nt], a, b[nt]);
                ap = &As2[(wm * 32 + mt * 16 + g) * SMPAD + k0 + tg];
                a[0] = ap[0]; a[1] = ap[8 * SMPAD]; a[2] = ap[4]; a[3] = ap[8 * SMPAD + 4];
                #pragma unroll
                for (int nt = 0; nt < 8; nt++) MMA_TF32(acc2[mt][nt], a, b[nt]);
            }
        }
        __syncthreads();
    }

    #pragma unroll
    for (int mt = 0; mt < 2; mt++) {
        #pragma unroll
        for (int nt = 0; nt < 8; nt++) {
            int col = n0 + wn * 64 + nt * 8 + tg * 2;
            if (col >= K_N) continue;
            size_t r0 = (size_t)(m0 + wm * 32 + mt * 16 + g);
            size_t r1 = r0 + 8;
            *(float2*)(O1 + r0 * K_N + col) = make_float2(acc1[mt][nt][0], acc1[mt][nt][1]);
            *(float2*)(O1 + r1 * K_N + col) = make_float2(acc1[mt][nt][2], acc1[mt][nt][3]);
            *(float2*)(O2 + r0 * K_N + col) = make_float2(acc2[mt][nt][0], acc2[mt][nt][1]);
            *(float2*)(O2 + r1 * K_N + col) = make_float2(acc2[mt][nt][2], acc2[mt][nt][3]);
        }
    }
}

// ---------------- host orchestration ----------------
extern "C" void kernel_launch(void* const* d_in, const int* in_sizes, int n_in,
                              void* d_out, int out_size) {
    (void)in_sizes; (void)n_in; (void)out_size;
    const int*   student_id  = (const int*)d_in[0];
    const int*   exercise_id = (const int*)d_in[1];
    const float* stu_emb     = (const float*)d_in[3];
    const float* exer_emb    = (const float*)d_in[4];
    const float* know_emb    = (const float*)d_in[5];
    const float* impact_emb  = (const float*)d_in[6];
    const int*   s_rows = (const int*)d_in[7];
    const int*   s_cols = (const int*)d_in[8];
    const float* s_vals = (const float*)d_in[9];
    const int*   e_rows = (const int*)d_in[10];
    const int*   e_cols = (const int*)d_in[11];
    const float* e_vals = (const float*)d_in[12];
    const int*   k_rows = (const int*)d_in[13];
    const int*   k_cols = (const int*)d_in[14];
    const float* k_vals = (const float*)d_in[15];
    const float* W_stu  = (const float*)d_in[16];
    const float* b_stu  = (const float*)d_in[17];
    const float* W_exer = (const float*)d_in[18];
    const float* b_exer = (const float*)d_in[19];
    const float* W_know = (const float*)d_in[20];
    const float* b_know = (const float*)d_in[21];
    const float* W_disc = (const float*)d_in[22];
    const float* b_disc = (const float*)d_in[23];

    unsigned char* A = nullptr;
    cudaGetSymbolAddress((void**)&A, g_arena);

    int*  rp_s  = (int*)(A + O_RP_S);
    int*  rp_e  = (int*)(A + O_RP_E);
    int*  rp_k  = (int*)(A + O_RP_K);
    int*  cur_s = (int*)(A + O_CUR_S);
    int*  cur_e = (int*)(A + O_CUR_E);
    int*  cur_k = (int*)(A + O_CUR_K);
    int*  bsums = (int*)(A + O_BSUMS);
    int2* pairs_s = (int2*)(A + O_PAIRS_S);
    int2* pairs_e = (int2*)(A + O_PAIRS_E);
    int2* pairs_k = (int2*)(A + O_PAIRS_K);
    float* x1_s = (float*)(A + O_X1_S);
    float* x2_s = (float*)(A + O_X2_S);
    float* x1_e = (float*)(A + O_X1_E);
    float* x2_e = (float*)(A + O_X2_E);
    float* x1_k = (float*)(A + O_X1_K);
    float* x2_k = (float*)(A + O_X2_K);
    float* x3_k = (float*)(A + O_X3_K);
    float* xg_s = (float*)(A + O_XG_S);
    float* xg_e = (float*)(A + O_XG_E);
    float* A1   = (float*)(A + O_A1);
    float* A2   = (float*)(A + O_A2);
    uint32_t* Bt32 = (uint32_t*)(A + O_BT32);

    // 1) CSR build
    zero_int_kernel<<<(ZERO_INTS + 1023) / 1024, 1024>>>(rp_s, ZERO_INTS);
    hist_all_kernel<<<(NNZ_TOT + 255) / 256, 256>>>(s_rows, e_rows, k_rows, rp_s, rp_e, rp_k);
    scan_block_all<<<NB_TOT, 1024>>>(rp_s, rp_e, rp_k, bsums);
    scan_bsums_all<<<1, 128>>>(bsums);
    scan_add_cursor_all<<<NB_TOT, 1024>>>(rp_s, rp_e, rp_k, cur_s, cur_e, cur_k, bsums);
    scatter_all_kernel<<<(NNZ_TOT + 255) / 256, 256>>>(
        s_rows, s_cols, s_vals, e_rows, e_cols, e_vals, k_rows, k_cols, k_vals,
        cur_s, cur_e, cur_k, pairs_s, pairs_e, pairs_k);

    // 2) layers 1-2 full; layer 3 batch-restricted (stu/exer) + full know
    const float* in_s[3] = {stu_emb, x1_s, x2_s};
    const float* in_e[3] = {exer_emb, x1_e, x2_e};
    const float* in_k[3] = {know_emb, x1_k, x2_k};
    for (int l = 0; l < 2; l++) {
        SpmmArgs sa;
        sa.rp[0] = rp_s;  sa.rp[1] = rp_e;  sa.rp[2] = rp_k;
        sa.pr[0] = pairs_s; sa.pr[1] = pairs_e; sa.pr[2] = pairs_k;
        sa.xin[0] = (const float4*)in_s[l]; sa.xin[1] = (const float4*)in_e[l]; sa.xin[2] = (const float4*)in_k[l];
        sa.xout[0] = (float4*)in_s[l + 1];  sa.xout[1] = (float4*)in_e[l + 1];  sa.xout[2] = (float4*)in_k[l + 1];
        sa.nrows[0] = S_N; sa.nrows[1] = E_N; sa.nrows[2] = K_N;
        spmm_all_kernel<<<GB_S + GB_E + GB_K, 256>>>(sa);
    }
    {
        Spmm3Args a3;
        a3.rp_s = rp_s; a3.pr_s = pairs_s; a3.x2_s = (const float4*)x2_s; a3.xg_s = (float4*)xg_s; a3.sid = student_id;
        a3.rp_e = rp_e; a3.pr_e = pairs_e; a3.x2_e = (const float4*)x2_e; a3.xg_e = (float4*)xg_e; a3.eid = exercise_id;
        a3.rp_k = rp_k; a3.pr_k = pairs_k; a3.x2_k = (const float4*)x2_k; a3.x3_k = (float4*)x3_k;
        spmm_l3_kernel<<<GL_S + GL_E + GL_K, 256>>>(a3);
    }

    // 3) output layout
    float* out   = (float*)d_out;
    float* O1    = out;
    float* O2    = O1 + (size_t)B_N * K_N;
    float* Odisc = O2 + (size_t)B_N * K_N;
    float* Okt   = Odisc + B_N;
    float* Oimp  = Okt + (size_t)K_N * FF;

    // 4) merged dense stage
    DenseArgs da;
    da.xs0 = stu_emb; da.xs1 = x1_s; da.xs2 = x2_s; da.xs3 = xg_s;
    da.xe0 = exer_emb; da.xe1 = x1_e; da.xe2 = x2_e; da.xe3 = xg_e;
    da.xk0 = know_emb; da.xk1 = x1_k; da.xk2 = x2_k; da.xk3 = x3_k;
    da.sid = student_id; da.eid = exercise_id;
    da.Ws = W_stu; da.bs = b_stu; da.We = W_exer; da.be = b_exer;
    da.Wk = W_know; da.bk = b_know; da.Wd = W_disc; da.bd = b_disc;
    da.imp = impact_emb;
    da.A1 = A1; da.A2 = A2; da.Okt = Okt; da.Odisc = Odisc; da.Oimp = Oimp;
    da.Bt32 = Bt32;
    dense_all_kernel<<<G_DENSE, 256>>>(da);

    // 5) TF32 big GEMM pair (128x128 tiles, padded B)
    static bool attr_set = false;
    if (!attr_set) {
        cudaFuncSetAttribute(big_gemm_tf32_dual,
                             cudaFuncAttributeMaxDynamicSharedMemorySize, GEMM_SMEM_BYTES);
        attr_set = true;
    }
    dim3 grid(B_N / 128, 1024 / 128);
    big_gemm_tf32_dual<<<grid, 256, GEMM_SMEM_BYTES>>>(
        (const uint32_t*)A1, (const uint32_t*)A2, Bt32, O1, O2);
}